// round 2
// baseline (speedup 1.0000x reference)
#include <cuda_runtime.h>

#define NT   365
#define NB   2048
#define NXD  32
#define HID  256
#define NG   1024   // 4*HID

// ---- device-global scratch (no cudaMalloc allowed) ----
__device__ float g_x0[(size_t)NT * NB * HID];   // relu(x @ w_in^T + b_in), 765 MB
__device__ float g_hbuf[2 * NB * HID];          // double-buffered h state
__device__ float g_c[NB * HID];                 // c state
__device__ float g_bias[NG];                    // b_ih + b_hh

// =====================================================================
// init: zero states, fold biases, preset out = b_out
// =====================================================================
__global__ void init_kernel(const float* __restrict__ b_ih,
                            const float* __restrict__ b_hh,
                            const float* __restrict__ b_out,
                            float* __restrict__ out) {
    int i = blockIdx.x * blockDim.x + threadIdx.x;
    int stride = gridDim.x * blockDim.x;
    for (int k = i; k < 2 * NB * HID; k += stride) g_hbuf[k] = 0.f;
    for (int k = i; k < NB * HID; k += stride) g_c[k] = 0.f;
    for (int k = i; k < NG; k += stride) g_bias[k] = b_ih[k] + b_hh[k];
    float b0 = b_out[0];
    for (int k = i; k < NT * NB; k += stride) out[k] = b0;
}

// =====================================================================
// input projection: x0 = relu(x @ w_in^T + b_in)
// block = 256 threads (one per hidden unit), 32 rows per block
// =====================================================================
__global__ void __launch_bounds__(256) input_proj(const float* __restrict__ x,
                                                  const float* __restrict__ w_in,
                                                  const float* __restrict__ b_in) {
    __shared__ float xs[32][NXD];
    int tid = threadIdx.x;
    size_t row0 = (size_t)blockIdx.x * 32;
    const float* xsrc = x + row0 * NXD;
#pragma unroll
    for (int r = 0; r < 4; ++r) {
        int lin = tid + r * 256;
        xs[lin >> 5][lin & 31] = xsrc[lin];
    }
    float w[NXD];
#pragma unroll
    for (int n = 0; n < NXD; ++n) w[n] = w_in[tid * NXD + n];
    float b = b_in[tid];
    __syncthreads();
    float* dst = g_x0 + row0 * HID + tid;
#pragma unroll 4
    for (int m = 0; m < 32; ++m) {
        float acc = b;
#pragma unroll
        for (int n = 0; n < NXD; ++n) acc = fmaf(xs[m][n], w[n], acc);
        dst[(size_t)m * HID] = fmaxf(acc, 0.f);
    }
}

// =====================================================================
// recurrent step:
//   gates[b, G] = sum_k [x0[t]|h_prev][b,k] * [w_ih|w_hh][G,k] + bias[G]
//   cell update + h_next + partial output dot (atomicAdd)
// Tile: 64 batch rows x 32 hidden units (= 128 gate columns).
// Gate column interleave: local col c -> gate g4 = c&3, unit jj = c>>2.
// 128 threads, each an 8(row) x 4(col-pair) micro-tile via fma.rn.f32x2.
// =====================================================================
__global__ void __launch_bounds__(128) lstm_step(const float* __restrict__ w_ih,
                                                 const float* __restrict__ w_hh,
                                                 const float* __restrict__ w_out,
                                                 float* __restrict__ out,
                                                 int t) {
    __shared__ float smem[64 * 132];          // 33.8 KB, reused for gate staging
    float* As = smem;                          // [64][32]
    float* Bs = smem + 64 * 32;                // [32][132] (pad 4 vs banks)

    int tid = threadIdx.x;
    int tx = tid & 15, ty = tid >> 4;          // 16 x 8
    int b0 = blockIdx.x * 64;
    int j0 = blockIdx.y * 32;

    const float* hin  = g_hbuf + (size_t)(t & 1) * NB * HID;
    float*       hout = g_hbuf + (size_t)((t + 1) & 1) * NB * HID;
    const float* x0t  = g_x0 + (size_t)t * NB * HID;

    unsigned long long acc2[8][4];
#pragma unroll
    for (int i = 0; i < 8; ++i)
#pragma unroll
        for (int p = 0; p < 4; ++p) acc2[i][p] = 0ull;

#pragma unroll 1
    for (int kt = 0; kt < 16; ++kt) {
        int phase = kt >> 3;
        int k0 = (kt & 7) * 32;
        const float* Aptr = phase ? hin : x0t;
        const float* W = phase ? w_hh : w_ih;

        // A tile: 64x32 floats, 4 float4 per thread, coalesced
#pragma unroll
        for (int r = 0; r < 4; ++r) {
            int lin = tid + r * 128;
            int m = lin >> 3, k4 = lin & 7;
            float4 v = *(const float4*)(Aptr + (size_t)(b0 + m) * HID + k0 + k4 * 4);
            *(float4*)(As + m * 32 + k4 * 4) = v;
        }
        // B tile: 128 cols x 32 k, transposed store into Bs[kk][c]
#pragma unroll
        for (int r = 0; r < 8; ++r) {
            int lin = tid + r * 128;
            int c = lin >> 3, k4 = lin & 7;
            int gidx = (c & 3) * HID + j0 + (c >> 2);
            float4 v = *(const float4*)(W + (size_t)gidx * HID + k0 + k4 * 4);
            float* bp = Bs + (k4 * 4) * 132 + c;
            bp[0] = v.x; bp[132] = v.y; bp[264] = v.z; bp[396] = v.w;
        }
        __syncthreads();

#pragma unroll 8
        for (int kk = 0; kk < 32; ++kk) {
            unsigned long long rb2[4], ra2[8];
#pragma unroll
            for (int p = 0; p < 4; ++p)
                rb2[p] = *(const unsigned long long*)(Bs + kk * 132 + ((p * 16 + tx) << 1));
#pragma unroll
            for (int i = 0; i < 8; ++i) {
                float a = As[(i * 8 + ty) * 32 + kk];
                asm("mov.b64 %0, {%1, %1};" : "=l"(ra2[i]) : "f"(a));
            }
#pragma unroll
            for (int i = 0; i < 8; ++i)
#pragma unroll
                for (int p = 0; p < 4; ++p)
                    asm("fma.rn.f32x2 %0, %1, %2, %0;"
                        : "+l"(acc2[i][p]) : "l"(ra2[i]), "l"(rb2[p]));
        }
        __syncthreads();
    }

    // stage gates to smem: gs[m][c], row stride 132
    float* gs = smem;
#pragma unroll
    for (int i = 0; i < 8; ++i)
#pragma unroll
        for (int p = 0; p < 4; ++p)
            *(unsigned long long*)(gs + (i * 8 + ty) * 132 + ((p * 16 + tx) << 1)) = acc2[i][p];
    __syncthreads();

    // cell update: thread -> one batch row m = tid>>1, 16 consecutive jj
    {
        int m = tid >> 1;
        int jbase = (tid & 1) * 16;
        int b = b0 + m;
        const float* gsr = gs + m * 132;
        float osum = 0.f;
#pragma unroll
        for (int s = 0; s < 16; ++s) {
            int jj = jbase + s;
            float4 gv = *(const float4*)(gsr + jj * 4);   // i,f,g,o interleaved
            int j = j0 + jj;
            float gi = gv.x + g_bias[j];
            float gf = gv.y + g_bias[HID + j];
            float gg = gv.z + g_bias[2 * HID + j];
            float go = gv.w + g_bias[3 * HID + j];
            float ii = 1.f / (1.f + __expf(-gi));
            float ff = 1.f / (1.f + __expf(-gf));
            float tg = tanhf(gg);
            float oo = 1.f / (1.f + __expf(-go));
            size_t idx = (size_t)b * HID + j;
            float cn = ff * g_c[idx] + ii * tg;
            float hn = oo * tanhf(cn);
            g_c[idx] = cn;
            hout[idx] = hn;
            osum = fmaf(hn, w_out[j], osum);
        }
        atomicAdd(out + (size_t)t * NB + b, osum);
    }
}

// =====================================================================
extern "C" void kernel_launch(void* const* d_in, const int* in_sizes, int n_in,
                              void* d_out, int out_size) {
    const float* x     = (const float*)d_in[0];
    const float* w_in  = (const float*)d_in[1];
    const float* b_in  = (const float*)d_in[2];
    const float* w_ih  = (const float*)d_in[3];
    const float* w_hh  = (const float*)d_in[4];
    const float* b_ih  = (const float*)d_in[5];
    const float* b_hh  = (const float*)d_in[6];
    const float* w_out = (const float*)d_in[7];
    const float* b_out = (const float*)d_in[8];
    float* out = (float*)d_out;

    init_kernel<<<1024, 256>>>(b_ih, b_hh, b_out, out);
    input_proj<<<(NT * NB) / 32, 256>>>(x, w_in, b_in);

    dim3 sgrid(NB / 64, HID / 32);
    for (int t = 0; t < NT; ++t) {
        lstm_step<<<sgrid, 128>>>(w_ih, w_hh, w_out, out, t);
    }
}

// round 8
// speedup vs baseline: 1.5070x; 1.5070x over previous
#include <cuda_runtime.h>
#include <cuda_bf16.h>
#include <cstdint>

#define NT 365
#define NB 2048
#define NXD 32
#define HID 256
#define NG 1024
#define TSPLIT 184

// ---- device-global scratch (no cudaMalloc allowed) ----
__device__ __nv_bfloat16 g_x0hi[(size_t)NT * NB * HID];   // 383 MB
__device__ __nv_bfloat16 g_x0lo[(size_t)NT * NB * HID];   // 383 MB
__device__ float g_gx0[(size_t)TSPLIT * NB * NG];         // 1.54 GB
__device__ float g_gx1[(size_t)(NT - TSPLIT) * NB * NG];  // 1.52 GB
__device__ __nv_bfloat16 g_hhi[2 * NB * HID];
__device__ __nv_bfloat16 g_hlo[2 * NB * HID];
__device__ float g_c[NB * HID];
__device__ __nv_bfloat16 g_wihHi[NG * HID], g_wihLo[NG * HID];  // permuted [C][k]
__device__ __nv_bfloat16 g_whhHi[NG * HID], g_whhLo[NG * HID];
__device__ float g_biasQ[NG];   // layout 4j+g

// =====================================================================
// mma.sync helpers (baseline PTX, no sm_103a-only features)
// =====================================================================
__device__ __forceinline__ void ldsm4(uint32_t (&r)[4], uint32_t addr) {
    asm volatile("ldmatrix.sync.aligned.m8n8.x4.shared.b16 {%0,%1,%2,%3}, [%4];"
                 : "=r"(r[0]), "=r"(r[1]), "=r"(r[2]), "=r"(r[3]) : "r"(addr));
}
__device__ __forceinline__ void mma16816(float (&d)[4], const uint32_t (&a)[4],
                                         uint32_t b0, uint32_t b1) {
    asm volatile("mma.sync.aligned.m16n8k16.row.col.f32.bf16.bf16.f32 "
                 "{%0,%1,%2,%3}, {%4,%5,%6,%7}, {%8,%9}, {%0,%1,%2,%3};"
                 : "+f"(d[0]), "+f"(d[1]), "+f"(d[2]), "+f"(d[3])
                 : "r"(a[0]), "r"(a[1]), "r"(a[2]), "r"(a[3]), "r"(b0), "r"(b1));
}
__device__ __forceinline__ uint32_t smem_u32(const void* p) {
    return (uint32_t)__cvta_generic_to_shared(p);
}

// =====================================================================
// Core 128x128 GEMM over virtual K=768 (3-phase hi/lo bf16).
// smem: 2 buffers x (A 128x32 + B 128x32), row stride 80B (conflict-free
// ldmatrix). Warp grid 2(M)x4(N), warp tile 64x32, m16n8k16 fragments.
// acc[mi][ni][r]: ni even = (i,f)-pair columns, ni odd = (g,o)-pair.
// =====================================================================
__device__ __forceinline__ void gemm_core(
    float acc[4][4][4],
    const __nv_bfloat16* __restrict__ Ahi, const __nv_bfloat16* __restrict__ Alo,
    size_t arow0,
    const __nv_bfloat16* __restrict__ Bhi, const __nv_bfloat16* __restrict__ Blo,
    size_t brow0,
    char* sm, int tid)
{
    const int lane = tid & 31, wid = tid >> 5;
    const int wm = wid >> 2, wn = wid & 3;
    const uint32_t sbase = smem_u32(sm);
    const int rowA = tid >> 2, seg = tid & 3;

#pragma unroll
    for (int a = 0; a < 4; ++a)
#pragma unroll
        for (int b = 0; b < 4; ++b)
#pragma unroll
            for (int r = 0; r < 4; ++r) acc[a][b][r] = 0.f;

    float4 pa0, pa1, pb0, pb1;
    pa0 = *(const float4*)(Ahi + arow0 + (size_t)rowA * HID + seg * 8);
    pa1 = *(const float4*)(Ahi + arow0 + (size_t)(rowA + 64) * HID + seg * 8);
    pb0 = *(const float4*)(Bhi + brow0 + (size_t)rowA * HID + seg * 8);
    pb1 = *(const float4*)(Bhi + brow0 + (size_t)(rowA + 64) * HID + seg * 8);
    *(float4*)(sm + rowA * 80 + seg * 16) = pa0;
    *(float4*)(sm + (rowA + 64) * 80 + seg * 16) = pa1;
    *(float4*)(sm + 10240 + rowA * 80 + seg * 16) = pb0;
    *(float4*)(sm + 10240 + (rowA + 64) * 80 + seg * 16) = pb1;
    __syncthreads();

#pragma unroll 1
    for (int kt = 0; kt < 24; ++kt) {
        if (kt < 23) {
            int nk = kt + 1;
            int ph = nk >> 3;                 // 0: hi*hi, 1: lo*hi, 2: hi*lo
            int k0 = (nk & 7) * 32;
            const __nv_bfloat16* As = (ph == 1) ? Alo : Ahi;
            const __nv_bfloat16* Bs = (ph == 2) ? Blo : Bhi;
            pa0 = *(const float4*)(As + arow0 + (size_t)rowA * HID + k0 + seg * 8);
            pa1 = *(const float4*)(As + arow0 + (size_t)(rowA + 64) * HID + k0 + seg * 8);
            pb0 = *(const float4*)(Bs + brow0 + (size_t)rowA * HID + k0 + seg * 8);
            pb1 = *(const float4*)(Bs + brow0 + (size_t)(rowA + 64) * HID + k0 + seg * 8);
        }
        uint32_t abase = sbase + (kt & 1) * 20480;
        uint32_t bbase = abase + 10240;
#pragma unroll
        for (int kk = 0; kk < 2; ++kk) {
            uint32_t af[4][4], bf[2][4];
#pragma unroll
            for (int mi = 0; mi < 4; ++mi)
                ldsm4(af[mi], abase + (wm * 64 + mi * 16 + (lane & 15)) * 80
                                    + kk * 32 + (lane >> 4) * 16);
#pragma unroll
            for (int np = 0; np < 2; ++np)
                ldsm4(bf[np], bbase + (wn * 32 + np * 16 + (lane & 15)) * 80
                                    + kk * 32 + (lane >> 4) * 16);
#pragma unroll
            for (int mi = 0; mi < 4; ++mi)
#pragma unroll
                for (int np = 0; np < 2; ++np) {
                    mma16816(acc[mi][2 * np],     af[mi], bf[np][0], bf[np][2]);
                    mma16816(acc[mi][2 * np + 1], af[mi], bf[np][1], bf[np][3]);
                }
        }
        if (kt < 23) {
            char* dst = sm + ((kt + 1) & 1) * 20480;
            *(float4*)(dst + rowA * 80 + seg * 16) = pa0;
            *(float4*)(dst + (rowA + 64) * 80 + seg * 16) = pa1;
            *(float4*)(dst + 10240 + rowA * 80 + seg * 16) = pb0;
            *(float4*)(dst + 10240 + (rowA + 64) * 80 + seg * 16) = pb1;
            __syncthreads();
        }
    }
}

// =====================================================================
// init: zero states, preset out = b_out
// =====================================================================
__global__ void init_kernel(const float* __restrict__ b_out, float* __restrict__ out) {
    int i = blockIdx.x * blockDim.x + threadIdx.x;
    int stride = gridDim.x * blockDim.x;
    __nv_bfloat16 z = __float2bfloat16(0.f);
    for (int k = i; k < 2 * NB * HID; k += stride) { g_hhi[k] = z; g_hlo[k] = z; }
    for (int k = i; k < NB * HID; k += stride) g_c[k] = 0.f;
    float b0 = b_out[0];
    for (int k = i; k < NT * NB; k += stride) out[k] = b0;
}

// =====================================================================
// weight prep: permute gate columns so warp fragments own whole units.
// permuted col C: bxc=C>>7, wn=(C>>5)&3, ni=(C>>3)&3, p=C&7
//   unit j = bxc*32 + wn*8 + (ni>>1)*4 + (p>>1),  gate g = ((ni&1)<<1)|(p&1)
// =====================================================================
__global__ void prep_w(const float* __restrict__ w_ih, const float* __restrict__ w_hh,
                       const float* __restrict__ b_ih, const float* __restrict__ b_hh) {
    int C = blockIdx.x, k = threadIdx.x;
    int bxc = C >> 7, r = C & 127;
    int wn = r >> 5, r2 = r & 31, ni = r2 >> 3, p = r2 & 7;
    int j = bxc * 32 + wn * 8 + (ni >> 1) * 4 + (p >> 1);
    int g = ((ni & 1) << 1) | (p & 1);
    int src = g * HID + j;
    float vih = w_ih[(size_t)src * HID + k];
    float vhh = w_hh[(size_t)src * HID + k];
    __nv_bfloat16 h1 = __float2bfloat16_rn(vih);
    g_wihHi[(size_t)C * HID + k] = h1;
    g_wihLo[(size_t)C * HID + k] = __float2bfloat16_rn(vih - __bfloat162float(h1));
    __nv_bfloat16 h2 = __float2bfloat16_rn(vhh);
    g_whhHi[(size_t)C * HID + k] = h2;
    g_whhLo[(size_t)C * HID + k] = __float2bfloat16_rn(vhh - __bfloat162float(h2));
    if (k == 0) g_biasQ[4 * j + g] = b_ih[src] + b_hh[src];
}

// =====================================================================
// input projection: x0 = relu(x @ w_in^T + b_in), written as bf16 hi/lo
// =====================================================================
__global__ void __launch_bounds__(256) input_proj(const float* __restrict__ x,
                                                  const float* __restrict__ w_in,
                                                  const float* __restrict__ b_in) {
    __shared__ float xs[32][NXD];
    int tid = threadIdx.x;
    size_t row0 = (size_t)blockIdx.x * 32;
    const float* xsrc = x + row0 * NXD;
#pragma unroll
    for (int r = 0; r < 4; ++r) {
        int lin = tid + r * 256;
        xs[lin >> 5][lin & 31] = xsrc[lin];
    }
    float w[NXD];
#pragma unroll
    for (int n = 0; n < NXD; ++n) w[n] = w_in[tid * NXD + n];
    float b = b_in[tid];
    __syncthreads();
    __nv_bfloat16* dh = g_x0hi + row0 * HID + tid;
    __nv_bfloat16* dl = g_x0lo + row0 * HID + tid;
#pragma unroll 4
    for (int m = 0; m < 32; ++m) {
        float acc = b;
#pragma unroll
        for (int n = 0; n < NXD; ++n) acc = fmaf(xs[m][n], w[n], acc);
        float v = fmaxf(acc, 0.f);
        __nv_bfloat16 hi = __float2bfloat16_rn(v);
        dh[(size_t)m * HID] = hi;
        dl[(size_t)m * HID] = __float2bfloat16_rn(v - __bfloat162float(hi));
    }
}

// =====================================================================
// pre-GEMM: gx[R][4j+g] = x0[R] . w_ihP + biasQ
// grid (8, 5840), 256 threads
// =====================================================================
__global__ void __launch_bounds__(256, 2) gemm_gx() {
    __shared__ __align__(16) char sm[40960];
    int tid = threadIdx.x, lane = tid & 31, wid = tid >> 5;
    int wm = wid >> 2, wn = wid & 3;
    int bx = blockIdx.x;
    size_t row0 = (size_t)blockIdx.y * 128;

    float acc[4][4][4];
    gemm_core(acc, g_x0hi, g_x0lo, row0 * HID,
              g_wihHi, g_wihLo, (size_t)bx * 128 * HID, sm, tid);

    float* gx; size_t R0;
    if (row0 < (size_t)TSPLIT * NB) { gx = g_gx0; R0 = row0; }
    else { gx = g_gx1; R0 = row0 - (size_t)TSPLIT * NB; }

    int q = lane >> 2;
#pragma unroll
    for (int np = 0; np < 2; ++np) {
        int jl = wn * 8 + np * 4 + (lane & 3);
        float4 bv = *(const float4*)(g_biasQ + bx * 128 + jl * 4);
#pragma unroll
        for (int mi = 0; mi < 4; ++mi) {
            size_t R = R0 + wm * 64 + mi * 16 + q;
#pragma unroll
            for (int hf = 0; hf < 2; ++hf) {
                float4 v;
                v.x = acc[mi][2 * np][2 * hf + 0] + bv.x;       // i
                v.y = acc[mi][2 * np][2 * hf + 1] + bv.y;       // f
                v.z = acc[mi][2 * np + 1][2 * hf + 0] + bv.z;   // g
                v.w = acc[mi][2 * np + 1][2 * hf + 1] + bv.w;   // o
                *(float4*)(gx + (R + hf * 8) * NG + bx * 128 + jl * 4) = v;
            }
        }
    }
}

// =====================================================================
// recurrent step: gates = gx[t] + h . w_hhP ; fused cell update epilogue
// grid (8, 16), 256 threads
// =====================================================================
__global__ void __launch_bounds__(256, 2) lstm_step(const float* __restrict__ w_out,
                                                    float* __restrict__ out, int t) {
    __shared__ __align__(16) char sm[40960];
    int tid = threadIdx.x, lane = tid & 31, wid = tid >> 5;
    int wm = wid >> 2, wn = wid & 3;
    int bx = blockIdx.x;
    int b0 = blockIdx.y * 128;

    const __nv_bfloat16* hhi = g_hhi + (size_t)(t & 1) * NB * HID;
    const __nv_bfloat16* hlo = g_hlo + (size_t)(t & 1) * NB * HID;
    __nv_bfloat16* hhiO = g_hhi + (size_t)((t + 1) & 1) * NB * HID;
    __nv_bfloat16* hloO = g_hlo + (size_t)((t + 1) & 1) * NB * HID;
    const float* gx = (t < TSPLIT) ? (g_gx0 + (size_t)t * NB * NG)
                                   : (g_gx1 + (size_t)(t - TSPLIT) * NB * NG);

    float acc[4][4][4];
    gemm_core(acc, hhi, hlo, (size_t)b0 * HID,
              g_whhHi, g_whhLo, (size_t)bx * 128 * HID, sm, tid);

    float osum[4][2];
#pragma unroll
    for (int mi = 0; mi < 4; ++mi) { osum[mi][0] = 0.f; osum[mi][1] = 0.f; }

    int q = lane >> 2;
#pragma unroll
    for (int np = 0; np < 2; ++np) {
        int jl = wn * 8 + np * 4 + (lane & 3);
        int j = bx * 32 + jl;
        float wo = w_out[j];
        const float* gxc = gx + bx * 128 + jl * 4;
#pragma unroll
        for (int mi = 0; mi < 4; ++mi) {
            int brow = b0 + wm * 64 + mi * 16 + q;
#pragma unroll
            for (int hf = 0; hf < 2; ++hf) {
                int b = brow + hf * 8;
                float4 gv = *(const float4*)(gxc + (size_t)b * NG);
                float gi = acc[mi][2 * np][2 * hf + 0] + gv.x;
                float gf = acc[mi][2 * np][2 * hf + 1] + gv.y;
                float gg = acc[mi][2 * np + 1][2 * hf + 0] + gv.z;
                float go = acc[mi][2 * np + 1][2 * hf + 1] + gv.w;
                float ii = 1.f / (1.f + __expf(-gi));
                float ff = 1.f / (1.f + __expf(-gf));
                float tg = tanhf(gg);
                float oo = 1.f / (1.f + __expf(-go));
                size_t idx = (size_t)b * HID + j;
                float cn = ff * g_c[idx] + ii * tg;
                float hn = oo * tanhf(cn);
                g_c[idx] = cn;
                __nv_bfloat16 hh = __float2bfloat16_rn(hn);
                hhiO[idx] = hh;
                hloO[idx] = __float2bfloat16_rn(hn - __bfloat162float(hh));
                osum[mi][hf] = fmaf(hn, wo, osum[mi][hf]);
            }
        }
    }
#pragma unroll
    for (int mi = 0; mi < 4; ++mi)
#pragma unroll
        for (int hf = 0; hf < 2; ++hf) {
            float v = osum[mi][hf];
            v += __shfl_xor_sync(0xffffffffu, v, 1);
            v += __shfl_xor_sync(0xffffffffu, v, 2);
            if ((lane & 3) == 0) {
                int b = b0 + wm * 64 + mi * 16 + q + hf * 8;
                atomicAdd(out + (size_t)t * NB + b, v);
            }
        }
}

// =====================================================================
extern "C" void kernel_launch(void* const* d_in, const int* in_sizes, int n_in,
                              void* d_out, int out_size) {
    const float* x     = (const float*)d_in[0];
    const float* w_in  = (const float*)d_in[1];
    const float* b_in  = (const float*)d_in[2];
    const float* w_ih  = (const float*)d_in[3];
    const float* w_hh  = (const float*)d_in[4];
    const float* b_ih  = (const float*)d_in[5];
    const float* b_hh  = (const float*)d_in[6];
    const float* w_out = (const float*)d_in[7];
    const float* b_out = (const float*)d_in[8];
    float* out = (float*)d_out;

    init_kernel<<<1024, 256>>>(b_out, out);
    prep_w<<<NG, HID>>>(w_ih, w_hh, b_ih, b_hh);
    input_proj<<<(NT * NB) / 32, 256>>>(x, w_in, b_in);
    gemm_gx<<<dim3(8, (NT * NB) / 128), 256>>>();

    for (int t = 0; t < NT; ++t)
        lstm_step<<<dim3(8, 16), 256>>>(w_out, out, t);
}

// round 9
// speedup vs baseline: 1.7416x; 1.1557x over previous
#include <cuda_runtime.h>
#include <cuda_bf16.h>
#include <cstdint>

#define NT 365
#define NB 2048
#define NXD 32
#define HID 256
#define NG 1024
#define TSPLIT 184
#define STAGES 4
#define SA_BYTES 10240                 // A stage: 128 rows * 80B
#define STG_GX (SA_BYTES + 10240)      // + B 128 rows
#define STG_ST (SA_BYTES + 5120)       // + B 64 rows
#define SMEM_GX (STAGES * STG_GX)      // 81920
#define SMEM_ST (STAGES * STG_ST)      // 61440

// ---- device-global scratch (no cudaMalloc allowed) ----
__device__ __nv_bfloat16 g_x0hi[(size_t)NT * NB * HID];
__device__ __nv_bfloat16 g_x0lo[(size_t)NT * NB * HID];
__device__ float g_gx0[(size_t)TSPLIT * NB * NG];
__device__ float g_gx1[(size_t)(NT - TSPLIT) * NB * NG];
__device__ __nv_bfloat16 g_hhi[2 * NB * HID];
__device__ __nv_bfloat16 g_hlo[2 * NB * HID];
__device__ float g_c[NB * HID];
__device__ __nv_bfloat16 g_wihHi[NG * HID], g_wihLo[NG * HID];  // permuted [C][k]
__device__ __nv_bfloat16 g_whhHi[NG * HID], g_whhLo[NG * HID];
__device__ float g_biasQ[NG];   // layout 4j+g

// =====================================================================
// baseline-PTX helpers (sm_80-era: ldmatrix / mma.sync / cp.async)
// =====================================================================
__device__ __forceinline__ void ldsm4(uint32_t (&r)[4], uint32_t addr) {
    asm volatile("ldmatrix.sync.aligned.m8n8.x4.shared.b16 {%0,%1,%2,%3}, [%4];"
                 : "=r"(r[0]), "=r"(r[1]), "=r"(r[2]), "=r"(r[3]) : "r"(addr));
}
__device__ __forceinline__ void mma16816(float (&d)[4], const uint32_t (&a)[4],
                                         uint32_t b0, uint32_t b1) {
    asm volatile("mma.sync.aligned.m16n8k16.row.col.f32.bf16.bf16.f32 "
                 "{%0,%1,%2,%3}, {%4,%5,%6,%7}, {%8,%9}, {%0,%1,%2,%3};"
                 : "+f"(d[0]), "+f"(d[1]), "+f"(d[2]), "+f"(d[3])
                 : "r"(a[0]), "r"(a[1]), "r"(a[2]), "r"(a[3]), "r"(b0), "r"(b1));
}
__device__ __forceinline__ uint32_t smem_u32(const void* p) {
    return (uint32_t)__cvta_generic_to_shared(p);
}
__device__ __forceinline__ void cp16(uint32_t dst, const void* src) {
    asm volatile("cp.async.cg.shared.global [%0], [%1], 16;" :: "r"(dst), "l"(src));
}
#define CPCOMMIT() asm volatile("cp.async.commit_group;" ::: "memory")
#define CPWAIT2()  asm volatile("cp.async.wait_group 2;" ::: "memory")

// =====================================================================
// Core 128 x (WN*32) GEMM over virtual K=768 (3-phase hi/lo bf16),
// cp.async 4-stage pipeline. Warp grid (8/WN) x WN, warp tile
// (WN*16 rows... WM=8/WN warps along M, each MI=WN m16-frags) x 32 cols.
// acc[mi][ni][r]: ni even = (i,f) column pair, ni odd = (g,o) pair.
// =====================================================================
template<int WN>
__device__ __forceinline__ void gemm_core(
    float (*acc)[4][4],
    const __nv_bfloat16* __restrict__ Ahi, const __nv_bfloat16* __restrict__ Alo,
    size_t arow0,
    const __nv_bfloat16* __restrict__ Bhi, const __nv_bfloat16* __restrict__ Blo,
    size_t brow0,
    char* sm, int tid)
{
    constexpr int MI = WN;             // m16-frags per warp (64 rows WN=4, 32 WN=2)
    constexpr int STG = SA_BYTES + WN * 32 * 80;
    const int lane = tid & 31, wid = tid >> 5;
    const int wm = wid / WN, wn = wid % WN;
    const uint32_t sbase = smem_u32(sm);
    const int rowT = tid >> 2, segT = tid & 3;   // cp.async chunk mapping

#pragma unroll
    for (int a = 0; a < MI; ++a)
#pragma unroll
        for (int b = 0; b < 4; ++b)
#pragma unroll
            for (int r = 0; r < 4; ++r) acc[a][b][r] = 0.f;

    // ---- stage issue helper (as lambda) ----
    auto issue = [&](int stage, int nk) {
        int ph = nk >> 3;                 // 0: hi*hi, 1: lo*hi, 2: hi*lo
        int k0 = (nk & 7) * 32;
        const __nv_bfloat16* As = (ph == 1) ? Alo : Ahi;
        const __nv_bfloat16* Bs = (ph == 2) ? Blo : Bhi;
        uint32_t dst = sbase + stage * STG;
#pragma unroll
        for (int i = 0; i < 2; ++i) {     // A: 128 rows x 4 segs = 512 chunks
            int id = tid + i * 256;
            int row = id >> 2, seg = id & 3;
            cp16(dst + row * 80 + seg * 16,
                 As + arow0 + (size_t)row * HID + k0 + seg * 8);
        }
#pragma unroll
        for (int i = 0; i < WN / 2; ++i) { // B: WN*32 rows x 4 segs
            int id = tid + i * 256;
            int row = id >> 2, seg = id & 3;
            cp16(dst + SA_BYTES + row * 80 + seg * 16,
                 Bs + brow0 + (size_t)row * HID + k0 + seg * 8);
        }
    };

#pragma unroll
    for (int s = 0; s < STAGES - 1; ++s) { issue(s, s); CPCOMMIT(); }

#pragma unroll 1
    for (int kt = 0; kt < 24; ++kt) {
        CPWAIT2();
        __syncthreads();
        if (kt + STAGES - 1 < 24) issue((kt + STAGES - 1) & (STAGES - 1), kt + STAGES - 1);
        CPCOMMIT();

        uint32_t abase = sbase + (kt & (STAGES - 1)) * STG;
        uint32_t bbase = abase + SA_BYTES;
#pragma unroll
        for (int kk = 0; kk < 2; ++kk) {
            uint32_t af[MI][4], bf[2][4];
#pragma unroll
            for (int mi = 0; mi < MI; ++mi)
                ldsm4(af[mi], abase + (wm * MI * 16 + mi * 16 + (lane & 15)) * 80
                                    + kk * 32 + (lane >> 4) * 16);
#pragma unroll
            for (int np = 0; np < 2; ++np)
                ldsm4(bf[np], bbase + (wn * 32 + np * 16 + (lane & 15)) * 80
                                    + kk * 32 + (lane >> 4) * 16);
#pragma unroll
            for (int mi = 0; mi < MI; ++mi)
#pragma unroll
                for (int np = 0; np < 2; ++np) {
                    mma16816(acc[mi][2 * np],     af[mi], bf[np][0], bf[np][2]);
                    mma16816(acc[mi][2 * np + 1], af[mi], bf[np][1], bf[np][3]);
                }
        }
        __syncthreads();   // all warps done with stage kt before it is refilled
    }
}

// =====================================================================
// init: zero states, preset out = b_out
// =====================================================================
__global__ void init_kernel(const float* __restrict__ b_out, float* __restrict__ out) {
    int i = blockIdx.x * blockDim.x + threadIdx.x;
    int stride = gridDim.x * blockDim.x;
    __nv_bfloat16 z = __float2bfloat16(0.f);
    for (int k = i; k < 2 * NB * HID; k += stride) { g_hhi[k] = z; g_hlo[k] = z; }
    for (int k = i; k < NB * HID; k += stride) g_c[k] = 0.f;
    float b0 = b_out[0];
    for (int k = i; k < NT * NB; k += stride) out[k] = b0;
}

// =====================================================================
// weight prep: permutation is purely C>>5-based (works for any tiling
// whose warp fragments are 32-col aligned):
//   blk32 = C>>5, ni = (C>>3)&3, p = C&7
//   unit j = blk32*8 + (ni>>1)*4 + (p>>1), gate g = ((ni&1)<<1)|(p&1)
// =====================================================================
__global__ void prep_w(const float* __restrict__ w_ih, const float* __restrict__ w_hh,
                       const float* __restrict__ b_ih, const float* __restrict__ b_hh) {
    int C = blockIdx.x, k = threadIdx.x;
    int blk32 = C >> 5, r2 = C & 31, ni = r2 >> 3, p = r2 & 7;
    int j = blk32 * 8 + (ni >> 1) * 4 + (p >> 1);
    int g = ((ni & 1) << 1) | (p & 1);
    int src = g * HID + j;
    float vih = w_ih[(size_t)src * HID + k];
    float vhh = w_hh[(size_t)src * HID + k];
    __nv_bfloat16 h1 = __float2bfloat16_rn(vih);
    g_wihHi[(size_t)C * HID + k] = h1;
    g_wihLo[(size_t)C * HID + k] = __float2bfloat16_rn(vih - __bfloat162float(h1));
    __nv_bfloat16 h2 = __float2bfloat16_rn(vhh);
    g_whhHi[(size_t)C * HID + k] = h2;
    g_whhLo[(size_t)C * HID + k] = __float2bfloat16_rn(vhh - __bfloat162float(h2));
    if (k == 0) g_biasQ[4 * j + g] = b_ih[src] + b_hh[src];
}

// =====================================================================
// input projection: x0 = relu(x @ w_in^T + b_in), written as bf16 hi/lo
// =====================================================================
__global__ void __launch_bounds__(256) input_proj(const float* __restrict__ x,
                                                  const float* __restrict__ w_in,
                                                  const float* __restrict__ b_in) {
    __shared__ float xs[32][NXD];
    int tid = threadIdx.x;
    size_t row0 = (size_t)blockIdx.x * 32;
    const float* xsrc = x + row0 * NXD;
#pragma unroll
    for (int r = 0; r < 4; ++r) {
        int lin = tid + r * 256;
        xs[lin >> 5][lin & 31] = xsrc[lin];
    }
    float w[NXD];
#pragma unroll
    for (int n = 0; n < NXD; ++n) w[n] = w_in[tid * NXD + n];
    float b = b_in[tid];
    __syncthreads();
    __nv_bfloat16* dh = g_x0hi + row0 * HID + tid;
    __nv_bfloat16* dl = g_x0lo + row0 * HID + tid;
#pragma unroll 4
    for (int m = 0; m < 32; ++m) {
        float acc = b;
#pragma unroll
        for (int n = 0; n < NXD; ++n) acc = fmaf(xs[m][n], w[n], acc);
        float v = fmaxf(acc, 0.f);
        __nv_bfloat16 hi = __float2bfloat16_rn(v);
        dh[(size_t)m * HID] = hi;
        dl[(size_t)m * HID] = __float2bfloat16_rn(v - __bfloat162float(hi));
    }
}

// =====================================================================
// pre-GEMM: gx[R][4j+g] = x0[R] . w_ihP + biasQ ; tiles 128x128
// grid (8, 5840), 256 threads
// =====================================================================
__global__ void __launch_bounds__(256, 2) gemm_gx() {
    extern __shared__ __align__(16) char sm[];
    int tid = threadIdx.x, lane = tid & 31, wid = tid >> 5;
    int wm = wid >> 2, wn = wid & 3;
    int bx = blockIdx.x;
    size_t row0 = (size_t)blockIdx.y * 128;

    float acc[4][4][4];
    gemm_core<4>(acc, g_x0hi, g_x0lo, row0 * HID,
                 g_wihHi, g_wihLo, (size_t)bx * 128 * HID, sm, tid);

    float* gx; size_t R0;
    if (row0 < (size_t)TSPLIT * NB) { gx = g_gx0; R0 = row0; }
    else { gx = g_gx1; R0 = row0 - (size_t)TSPLIT * NB; }

    int q = lane >> 2;
#pragma unroll
    for (int np = 0; np < 2; ++np) {
        int jl = wn * 8 + np * 4 + (lane & 3);
        float4 bv = *(const float4*)(g_biasQ + bx * 128 + jl * 4);
#pragma unroll
        for (int mi = 0; mi < 4; ++mi) {
            size_t R = R0 + wm * 64 + mi * 16 + q;
#pragma unroll
            for (int hf = 0; hf < 2; ++hf) {
                float4 v;
                v.x = acc[mi][2 * np][2 * hf + 0] + bv.x;       // i
                v.y = acc[mi][2 * np][2 * hf + 1] + bv.y;       // f
                v.z = acc[mi][2 * np + 1][2 * hf + 0] + bv.z;   // g
                v.w = acc[mi][2 * np + 1][2 * hf + 1] + bv.w;   // o
                *(float4*)(gx + (R + hf * 8) * NG + bx * 128 + jl * 4) = v;
            }
        }
    }
}

// =====================================================================
// recurrent step: gates = gx[t] + h . w_hhP ; tiles 128x64
// grid (16, 16), 256 threads; fused cell update epilogue
// =====================================================================
__global__ void __launch_bounds__(256, 2) lstm_step(const float* __restrict__ w_out,
                                                    float* __restrict__ out, int t) {
    extern __shared__ __align__(16) char sm[];
    int tid = threadIdx.x, lane = tid & 31, wid = tid >> 5;
    int wm = wid >> 1, wn = wid & 1;
    int bx = blockIdx.x;
    int b0 = blockIdx.y * 128;

    const __nv_bfloat16* hhi = g_hhi + (size_t)(t & 1) * NB * HID;
    const __nv_bfloat16* hlo = g_hlo + (size_t)(t & 1) * NB * HID;
    __nv_bfloat16* hhiO = g_hhi + (size_t)((t + 1) & 1) * NB * HID;
    __nv_bfloat16* hloO = g_hlo + (size_t)((t + 1) & 1) * NB * HID;
    const float* gx = (t < TSPLIT) ? (g_gx0 + (size_t)t * NB * NG)
                                   : (g_gx1 + (size_t)(t - TSPLIT) * NB * NG);

    float acc[2][4][4];
    gemm_core<2>(acc, hhi, hlo, (size_t)b0 * HID,
                 g_whhHi, g_whhLo, (size_t)bx * 64 * HID, sm, tid);

    float osum[2][2];
    osum[0][0] = osum[0][1] = osum[1][0] = osum[1][1] = 0.f;

    int q = lane >> 2, l2 = lane & 3;
#pragma unroll
    for (int np = 0; np < 2; ++np) {
        int j = bx * 16 + wn * 8 + np * 4 + l2;
        float wo = w_out[j];
#pragma unroll
        for (int mi = 0; mi < 2; ++mi) {
#pragma unroll
            for (int hf = 0; hf < 2; ++hf) {
                int b = b0 + wm * 32 + mi * 16 + q + hf * 8;
                float4 gv = *(const float4*)(gx + (size_t)b * NG + j * 4);
                float gi = acc[mi][2 * np][2 * hf + 0] + gv.x;
                float gf = acc[mi][2 * np][2 * hf + 1] + gv.y;
                float gg = acc[mi][2 * np + 1][2 * hf + 0] + gv.z;
                float go = acc[mi][2 * np + 1][2 * hf + 1] + gv.w;
                float ii = 1.f / (1.f + __expf(-gi));
                float ff = 1.f / (1.f + __expf(-gf));
                float tg = tanhf(gg);
                float oo = 1.f / (1.f + __expf(-go));
                size_t idx = (size_t)b * HID + j;
                float cn = ff * g_c[idx] + ii * tg;
                float hn = oo * tanhf(cn);
                g_c[idx] = cn;
                __nv_bfloat16 hh = __float2bfloat16_rn(hn);
                hhiO[idx] = hh;
                hloO[idx] = __float2bfloat16_rn(hn - __bfloat162float(hh));
                osum[mi][hf] = fmaf(hn, wo, osum[mi][hf]);
            }
        }
    }
#pragma unroll
    for (int mi = 0; mi < 2; ++mi)
#pragma unroll
        for (int hf = 0; hf < 2; ++hf) {
            float v = osum[mi][hf];
            v += __shfl_xor_sync(0xffffffffu, v, 1);
            v += __shfl_xor_sync(0xffffffffu, v, 2);
            if (l2 == 0) {
                int b = b0 + wm * 32 + mi * 16 + q + hf * 8;
                atomicAdd(out + (size_t)t * NB + b, v);
            }
        }
}

// =====================================================================
extern "C" void kernel_launch(void* const* d_in, const int* in_sizes, int n_in,
                              void* d_out, int out_size) {
    const float* x     = (const float*)d_in[0];
    const float* w_in  = (const float*)d_in[1];
    const float* b_in  = (const float*)d_in[2];
    const float* w_ih  = (const float*)d_in[3];
    const float* w_hh  = (const float*)d_in[4];
    const float* b_ih  = (const float*)d_in[5];
    const float* b_hh  = (const float*)d_in[6];
    const float* w_out = (const float*)d_in[7];
    const float* b_out = (const float*)d_in[8];
    float* out = (float*)d_out;

    static bool attr_done = false;
    if (!attr_done) {
        cudaFuncSetAttribute(gemm_gx, cudaFuncAttributeMaxDynamicSharedMemorySize, SMEM_GX);
        cudaFuncSetAttribute(lstm_step, cudaFuncAttributeMaxDynamicSharedMemorySize, SMEM_ST);
        attr_done = true;
    }

    init_kernel<<<1024, 256>>>(b_out, out);
    prep_w<<<NG, HID>>>(w_ih, w_hh, b_ih, b_hh);
    input_proj<<<(NT * NB) / 32, 256>>>(x, w_in, b_in);
    gemm_gx<<<dim3(8, (NT * NB) / 128), 256, SMEM_GX>>>();

    for (int t = 0; t < NT; ++t)
        lstm_step<<<dim3(16, 16), 256, SMEM_ST>>>(w_out, out, t);
}

// round 10
// speedup vs baseline: 2.0544x; 1.1796x over previous
#include <cuda_runtime.h>
#include <cuda_bf16.h>
#include <cstdint>

#define NT 365
#define NB 2048
#define NXD 32
#define HID 256
#define NG 1024
#define TSPLIT 184
#define STAGES 4
#define SA_BYTES 10240                 // A stage: 128 rows * 80B
#define STG_GX (SA_BYTES + 10240)      // + B 128 rows (gemm_gx only)
#define SMEM_GX (STAGES * STG_GX)      // 81920
// persistent step kernel smem: 4 A-stages + resident Whi/Wlo (64 x 528B each)
#define WROW 528
#define WSLAB (64 * WROW)              // 33792
#define SMEM_PS (STAGES * SA_BYTES + 2 * WSLAB)   // 40960 + 67584 = 108544

// ---- device-global scratch (no cudaMalloc allowed) ----
__device__ __nv_bfloat16 g_x0hi[(size_t)NT * NB * HID];
__device__ __nv_bfloat16 g_x0lo[(size_t)NT * NB * HID];
__device__ float g_gx0[(size_t)TSPLIT * NB * NG];
__device__ float g_gx1[(size_t)(NT - TSPLIT) * NB * NG];
__device__ __nv_bfloat16 g_hhi[2 * NB * HID];
__device__ __nv_bfloat16 g_hlo[2 * NB * HID];
__device__ __nv_bfloat16 g_wihHi[NG * HID], g_wihLo[NG * HID];  // permuted [C][k]
__device__ __nv_bfloat16 g_whhHi[NG * HID], g_whhLo[NG * HID];
__device__ float g_biasQ[NG];   // layout 4j+g
__device__ unsigned g_bar;      // grid barrier arrival counter
__device__ unsigned g_epoch;    // grid barrier epoch (released step count)

// =====================================================================
// baseline-PTX helpers (sm_80-era: ldmatrix / mma.sync / cp.async)
// =====================================================================
__device__ __forceinline__ void ldsm4(uint32_t (&r)[4], uint32_t addr) {
    asm volatile("ldmatrix.sync.aligned.m8n8.x4.shared.b16 {%0,%1,%2,%3}, [%4];"
                 : "=r"(r[0]), "=r"(r[1]), "=r"(r[2]), "=r"(r[3]) : "r"(addr));
}
__device__ __forceinline__ void mma16816(float (&d)[4], const uint32_t (&a)[4],
                                         uint32_t b0, uint32_t b1) {
    asm volatile("mma.sync.aligned.m16n8k16.row.col.f32.bf16.bf16.f32 "
                 "{%0,%1,%2,%3}, {%4,%5,%6,%7}, {%8,%9}, {%0,%1,%2,%3};"
                 : "+f"(d[0]), "+f"(d[1]), "+f"(d[2]), "+f"(d[3])
                 : "r"(a[0]), "r"(a[1]), "r"(a[2]), "r"(a[3]), "r"(b0), "r"(b1));
}
__device__ __forceinline__ uint32_t smem_u32(const void* p) {
    return (uint32_t)__cvta_generic_to_shared(p);
}
__device__ __forceinline__ void cp16(uint32_t dst, const void* src) {
    asm volatile("cp.async.cg.shared.global [%0], [%1], 16;" :: "r"(dst), "l"(src));
}
#define CPCOMMIT() asm volatile("cp.async.commit_group;" ::: "memory")
#define CPWAIT2()  asm volatile("cp.async.wait_group 2;" ::: "memory")

// =====================================================================
// gemm_gx core: 128x128 GEMM over virtual K=768 (3-phase hi/lo bf16),
// cp.async 4-stage pipeline, A and B both streamed (unchanged from R8).
// =====================================================================
__device__ __forceinline__ void gemm_core_gx(
    float (*acc)[4][4],
    const __nv_bfloat16* __restrict__ Ahi, const __nv_bfloat16* __restrict__ Alo,
    size_t arow0,
    const __nv_bfloat16* __restrict__ Bhi, const __nv_bfloat16* __restrict__ Blo,
    size_t brow0,
    char* sm, int tid)
{
    const int lane = tid & 31, wid = tid >> 5;
    const int wm = wid >> 2, wn = wid & 3;
    const uint32_t sbase = smem_u32(sm);

#pragma unroll
    for (int a = 0; a < 4; ++a)
#pragma unroll
        for (int b = 0; b < 4; ++b)
#pragma unroll
            for (int r = 0; r < 4; ++r) acc[a][b][r] = 0.f;

    auto issue = [&](int stage, int nk) {
        int ph = nk >> 3;
        int k0 = (nk & 7) * 32;
        const __nv_bfloat16* As = (ph == 1) ? Alo : Ahi;
        const __nv_bfloat16* Bs = (ph == 2) ? Blo : Bhi;
        uint32_t dst = sbase + stage * STG_GX;
#pragma unroll
        for (int i = 0; i < 2; ++i) {
            int id = tid + i * 256;
            int row = id >> 2, seg = id & 3;
            cp16(dst + row * 80 + seg * 16,
                 As + arow0 + (size_t)row * HID + k0 + seg * 8);
        }
#pragma unroll
        for (int i = 0; i < 2; ++i) {
            int id = tid + i * 256;
            int row = id >> 2, seg = id & 3;
            cp16(dst + SA_BYTES + row * 80 + seg * 16,
                 Bs + brow0 + (size_t)row * HID + k0 + seg * 8);
        }
    };

#pragma unroll
    for (int s = 0; s < STAGES - 1; ++s) { issue(s, s); CPCOMMIT(); }

#pragma unroll 1
    for (int kt = 0; kt < 24; ++kt) {
        CPWAIT2();
        __syncthreads();
        if (kt + STAGES - 1 < 24) issue((kt + STAGES - 1) & (STAGES - 1), kt + STAGES - 1);
        CPCOMMIT();

        uint32_t abase = sbase + (kt & (STAGES - 1)) * STG_GX;
        uint32_t bbase = abase + SA_BYTES;
#pragma unroll
        for (int kk = 0; kk < 2; ++kk) {
            uint32_t af[4][4], bf[2][4];
#pragma unroll
            for (int mi = 0; mi < 4; ++mi)
                ldsm4(af[mi], abase + (wm * 64 + mi * 16 + (lane & 15)) * 80
                                    + kk * 32 + (lane >> 4) * 16);
#pragma unroll
            for (int np = 0; np < 2; ++np)
                ldsm4(bf[np], bbase + (wn * 32 + np * 16 + (lane & 15)) * 80
                                    + kk * 32 + (lane >> 4) * 16);
#pragma unroll
            for (int mi = 0; mi < 4; ++mi)
#pragma unroll
                for (int np = 0; np < 2; ++np) {
                    mma16816(acc[mi][2 * np],     af[mi], bf[np][0], bf[np][2]);
                    mma16816(acc[mi][2 * np + 1], af[mi], bf[np][1], bf[np][3]);
                }
        }
        __syncthreads();
    }
}

// =====================================================================
// init: zero h buffers, reset barrier, preset out = b_out
// =====================================================================
__global__ void init_kernel(const float* __restrict__ b_out, float* __restrict__ out) {
    int i = blockIdx.x * blockDim.x + threadIdx.x;
    int stride = gridDim.x * blockDim.x;
    __nv_bfloat16 z = __float2bfloat16(0.f);
    for (int k = i; k < 2 * NB * HID; k += stride) { g_hhi[k] = z; g_hlo[k] = z; }
    float b0 = b_out[0];
    for (int k = i; k < NT * NB; k += stride) out[k] = b0;
    if (i == 0) { g_bar = 0; g_epoch = 0; }
}

// =====================================================================
// weight prep (unchanged): C>>5-based gate permutation + hi/lo split
// =====================================================================
__global__ void prep_w(const float* __restrict__ w_ih, const float* __restrict__ w_hh,
                       const float* __restrict__ b_ih, const float* __restrict__ b_hh) {
    int C = blockIdx.x, k = threadIdx.x;
    int blk32 = C >> 5, r2 = C & 31, ni = r2 >> 3, p = r2 & 7;
    int j = blk32 * 8 + (ni >> 1) * 4 + (p >> 1);
    int g = ((ni & 1) << 1) | (p & 1);
    int src = g * HID + j;
    float vih = w_ih[(size_t)src * HID + k];
    float vhh = w_hh[(size_t)src * HID + k];
    __nv_bfloat16 h1 = __float2bfloat16_rn(vih);
    g_wihHi[(size_t)C * HID + k] = h1;
    g_wihLo[(size_t)C * HID + k] = __float2bfloat16_rn(vih - __bfloat162float(h1));
    __nv_bfloat16 h2 = __float2bfloat16_rn(vhh);
    g_whhHi[(size_t)C * HID + k] = h2;
    g_whhLo[(size_t)C * HID + k] = __float2bfloat16_rn(vhh - __bfloat162float(h2));
    if (k == 0) g_biasQ[4 * j + g] = b_ih[src] + b_hh[src];
}

// =====================================================================
// input projection (unchanged)
// =====================================================================
__global__ void __launch_bounds__(256) input_proj(const float* __restrict__ x,
                                                  const float* __restrict__ w_in,
                                                  const float* __restrict__ b_in) {
    __shared__ float xs[32][NXD];
    int tid = threadIdx.x;
    size_t row0 = (size_t)blockIdx.x * 32;
    const float* xsrc = x + row0 * NXD;
#pragma unroll
    for (int r = 0; r < 4; ++r) {
        int lin = tid + r * 256;
        xs[lin >> 5][lin & 31] = xsrc[lin];
    }
    float w[NXD];
#pragma unroll
    for (int n = 0; n < NXD; ++n) w[n] = w_in[tid * NXD + n];
    float b = b_in[tid];
    __syncthreads();
    __nv_bfloat16* dh = g_x0hi + row0 * HID + tid;
    __nv_bfloat16* dl = g_x0lo + row0 * HID + tid;
#pragma unroll 4
    for (int m = 0; m < 32; ++m) {
        float acc = b;
#pragma unroll
        for (int n = 0; n < NXD; ++n) acc = fmaf(xs[m][n], w[n], acc);
        float v = fmaxf(acc, 0.f);
        __nv_bfloat16 hi = __float2bfloat16_rn(v);
        dh[(size_t)m * HID] = hi;
        dl[(size_t)m * HID] = __float2bfloat16_rn(v - __bfloat162float(hi));
    }
}

// =====================================================================
// pre-GEMM: gx[R][4j+g] = x0[R] . w_ihP + biasQ ; tiles 128x128
// =====================================================================
__global__ void __launch_bounds__(256, 2) gemm_gx() {
    extern __shared__ __align__(16) char sm[];
    int tid = threadIdx.x, lane = tid & 31, wid = tid >> 5;
    int wm = wid >> 2, wn = wid & 3;
    int bx = blockIdx.x;
    size_t row0 = (size_t)blockIdx.y * 128;

    float acc[4][4][4];
    gemm_core_gx(acc, g_x0hi, g_x0lo, row0 * HID,
                 g_wihHi, g_wihLo, (size_t)bx * 128 * HID, sm, tid);

    float* gx; size_t R0;
    if (row0 < (size_t)TSPLIT * NB) { gx = g_gx0; R0 = row0; }
    else { gx = g_gx1; R0 = row0 - (size_t)TSPLIT * NB; }

    int q = lane >> 2;
#pragma unroll
    for (int np = 0; np < 2; ++np) {
        int jl = wn * 8 + np * 4 + (lane & 3);
        float4 bv = *(const float4*)(g_biasQ + bx * 128 + jl * 4);
#pragma unroll
        for (int mi = 0; mi < 4; ++mi) {
            size_t R = R0 + wm * 64 + mi * 16 + q;
#pragma unroll
            for (int hf = 0; hf < 2; ++hf) {
                float4 v;
                v.x = acc[mi][2 * np][2 * hf + 0] + bv.x;
                v.y = acc[mi][2 * np][2 * hf + 1] + bv.y;
                v.z = acc[mi][2 * np + 1][2 * hf + 0] + bv.z;
                v.w = acc[mi][2 * np + 1][2 * hf + 1] + bv.w;
                *(float4*)(gx + (R + hf * 8) * NG + bx * 128 + jl * 4) = v;
            }
        }
    }
}

// =====================================================================
// PERSISTENT recurrent kernel: all 365 steps in one launch.
// 256 CTAs (bx = cta>>4 : 16 col-tiles of 64 gate-cols, by = cta&15 :
// 16 batch-tiles of 128 rows). w_hh hi/lo resident in smem; h streamed
// via cp.async; c in registers; device-wide barrier between steps.
// =====================================================================
__global__ void __launch_bounds__(256, 2) lstm_persist(const float* __restrict__ w_out,
                                                       float* __restrict__ out) {
    extern __shared__ __align__(16) char sm[];
    // [0, 40960): 4 A stages ; [40960, +33792): Whi ; then Wlo
    char* wsm = sm + STAGES * SA_BYTES;
    const uint32_t sbase = smem_u32(sm);
    const uint32_t wbase = sbase + STAGES * SA_BYTES;

    int tid = threadIdx.x, lane = tid & 31, wid = tid >> 5;
    int wm = wid >> 1, wn = wid & 1;
    int cta = blockIdx.x;
    int bx = cta >> 4, by = cta & 15;
    int b0 = by * 128;
    int q = lane >> 2, l2 = lane & 3;

    // ---- load resident weight slabs (64 cols x 256 k, hi & lo) ----
    {
        const __nv_bfloat16* WH = g_whhHi + (size_t)bx * 64 * HID;
        const __nv_bfloat16* WL = g_whhLo + (size_t)bx * 64 * HID;
#pragma unroll
        for (int i = 0; i < 8; ++i) {
            int id = tid + i * 256;          // 2048 16B-chunks per slab
            int row = id >> 5, seg = id & 31;
            *(float4*)(wsm + row * WROW + seg * 16) =
                *(const float4*)(WH + (size_t)row * HID + seg * 8);
            *(float4*)(wsm + WSLAB + row * WROW + seg * 16) =
                *(const float4*)(WL + (size_t)row * HID + seg * 8);
        }
    }
    __syncthreads();

    // ---- persistent per-thread state ----
    float creg[8];
#pragma unroll
    for (int i = 0; i < 8; ++i) creg[i] = 0.f;
    float wo[2];
#pragma unroll
    for (int np = 0; np < 2; ++np) wo[np] = w_out[bx * 16 + wn * 8 + np * 4 + l2];

#pragma unroll 1
    for (int t = 0; t < NT; ++t) {
        const __nv_bfloat16* hhi = g_hhi + (size_t)(t & 1) * NB * HID;
        const __nv_bfloat16* hlo = g_hlo + (size_t)(t & 1) * NB * HID;
        __nv_bfloat16* hhiO = g_hhi + (size_t)((t + 1) & 1) * NB * HID;
        __nv_bfloat16* hloO = g_hlo + (size_t)((t + 1) & 1) * NB * HID;
        const float* gx = (t < TSPLIT) ? (g_gx0 + (size_t)t * NB * NG)
                                       : (g_gx1 + (size_t)(t - TSPLIT) * NB * NG);

        float acc[2][4][4];
#pragma unroll
        for (int a = 0; a < 2; ++a)
#pragma unroll
            for (int b = 0; b < 4; ++b)
#pragma unroll
                for (int r = 0; r < 4; ++r) acc[a][b][r] = 0.f;

        auto issueA = [&](int stage, int nk) {
            int ph = nk >> 3;
            int k0 = (nk & 7) * 32;
            const __nv_bfloat16* As = (ph == 1) ? hlo : hhi;
            uint32_t dst = sbase + stage * SA_BYTES;
#pragma unroll
            for (int i = 0; i < 2; ++i) {
                int id = tid + i * 256;
                int row = id >> 2, seg = id & 3;
                cp16(dst + row * 80 + seg * 16,
                     As + (size_t)(b0 + row) * HID + k0 + seg * 8);
            }
        };

#pragma unroll
        for (int s = 0; s < STAGES - 1; ++s) { issueA(s, s); CPCOMMIT(); }

#pragma unroll 1
        for (int kt = 0; kt < 24; ++kt) {
            CPWAIT2();
            __syncthreads();
            if (kt + STAGES - 1 < 24) issueA((kt + STAGES - 1) & (STAGES - 1), kt + STAGES - 1);
            CPCOMMIT();

            uint32_t abase = sbase + (kt & (STAGES - 1)) * SA_BYTES;
            int ph = kt >> 3;
            uint32_t bb = wbase + (ph == 2 ? WSLAB : 0);
            int k0b = (kt & 7) * 64;       // byte offset into 512B weight row
#pragma unroll
            for (int kk = 0; kk < 2; ++kk) {
                uint32_t af[2][4], bf[2][4];
#pragma unroll
                for (int mi = 0; mi < 2; ++mi)
                    ldsm4(af[mi], abase + (wm * 32 + mi * 16 + (lane & 15)) * 80
                                        + kk * 32 + (lane >> 4) * 16);
#pragma unroll
                for (int np = 0; np < 2; ++np)
                    ldsm4(bf[np], bb + (wn * 32 + np * 16 + (lane & 15)) * WROW
                                     + k0b + kk * 32 + (lane >> 4) * 16);
#pragma unroll
                for (int mi = 0; mi < 2; ++mi)
#pragma unroll
                    for (int np = 0; np < 2; ++np) {
                        mma16816(acc[mi][2 * np],     af[mi], bf[np][0], bf[np][2]);
                        mma16816(acc[mi][2 * np + 1], af[mi], bf[np][1], bf[np][3]);
                    }
            }
            __syncthreads();
        }

        // ---- fused epilogue: gates -> cell update (c in regs) ----
        float osum[2][2];
        osum[0][0] = osum[0][1] = osum[1][0] = osum[1][1] = 0.f;
#pragma unroll
        for (int np = 0; np < 2; ++np) {
            int j = bx * 16 + wn * 8 + np * 4 + l2;
#pragma unroll
            for (int mi = 0; mi < 2; ++mi) {
#pragma unroll
                for (int hf = 0; hf < 2; ++hf) {
                    int b = b0 + wm * 32 + mi * 16 + q + hf * 8;
                    float4 gv = *(const float4*)(gx + (size_t)b * NG + j * 4);
                    float gi = acc[mi][2 * np][2 * hf + 0] + gv.x;
                    float gf = acc[mi][2 * np][2 * hf + 1] + gv.y;
                    float gg = acc[mi][2 * np + 1][2 * hf + 0] + gv.z;
                    float go = acc[mi][2 * np + 1][2 * hf + 1] + gv.w;
                    float ii = 1.f / (1.f + __expf(-gi));
                    float ff = 1.f / (1.f + __expf(-gf));
                    float tg = tanhf(gg);
                    float oo = 1.f / (1.f + __expf(-go));
                    int ci = np * 4 + mi * 2 + hf;
                    float cn = ff * creg[ci] + ii * tg;
                    float hn = oo * tanhf(cn);
                    creg[ci] = cn;
                    size_t idx = (size_t)b * HID + j;
                    __nv_bfloat16 hh = __float2bfloat16_rn(hn);
                    hhiO[idx] = hh;
                    hloO[idx] = __float2bfloat16_rn(hn - __bfloat162float(hh));
                    osum[mi][hf] = fmaf(hn, wo[np], osum[mi][hf]);
                }
            }
        }
#pragma unroll
        for (int mi = 0; mi < 2; ++mi)
#pragma unroll
            for (int hf = 0; hf < 2; ++hf) {
                float v = osum[mi][hf];
                v += __shfl_xor_sync(0xffffffffu, v, 1);
                v += __shfl_xor_sync(0xffffffffu, v, 2);
                if (l2 == 0) {
                    int b = b0 + wm * 32 + mi * 16 + q + hf * 8;
                    atomicAdd(out + (size_t)t * NB + b, v);
                }
            }

        // ---- device-wide barrier (h must be globally visible) ----
        if (t < NT - 1) {
            __syncthreads();
            if (tid == 0) {
                __threadfence();
                unsigned arr = atomicAdd(&g_bar, 1);
                if (arr == (unsigned)(gridDim.x - 1)) {
                    g_bar = 0;
                    __threadfence();
                    atomicExch(&g_epoch, (unsigned)(t + 1));
                } else {
                    unsigned e;
                    do {
                        __nanosleep(64);
                        asm volatile("ld.acquire.gpu.u32 %0, [%1];"
                                     : "=r"(e) : "l"(&g_epoch) : "memory");
                    } while (e < (unsigned)(t + 1));
                }
            }
            __syncthreads();
        }
    }
}

// =====================================================================
extern "C" void kernel_launch(void* const* d_in, const int* in_sizes, int n_in,
                              void* d_out, int out_size) {
    const float* x     = (const float*)d_in[0];
    const float* w_in  = (const float*)d_in[1];
    const float* b_in  = (const float*)d_in[2];
    const float* w_ih  = (const float*)d_in[3];
    const float* w_hh  = (const float*)d_in[4];
    const float* b_ih  = (const float*)d_in[5];
    const float* b_hh  = (const float*)d_in[6];
    const float* w_out = (const float*)d_in[7];
    const float* b_out = (const float*)d_in[8];
    float* out = (float*)d_out;

    static bool attr_done = false;
    if (!attr_done) {
        cudaFuncSetAttribute(gemm_gx, cudaFuncAttributeMaxDynamicSharedMemorySize, SMEM_GX);
        cudaFuncSetAttribute(lstm_persist, cudaFuncAttributeMaxDynamicSharedMemorySize, SMEM_PS);
        attr_done = true;
    }

    init_kernel<<<1024, 256>>>(b_out, out);
    prep_w<<<NG, HID>>>(w_ih, w_hh, b_ih, b_hh);
    input_proj<<<(NT * NB) / 32, 256>>>(x, w_in, b_in);
    gemm_gx<<<dim3(8, (NT * NB) / 128), 256, SMEM_GX>>>();
    lstm_persist<<<256, 256, SMEM_PS>>>(w_out, out);
}

// round 12
// speedup vs baseline: 2.0709x; 1.0080x over previous
#include <cuda_runtime.h>
#include <cuda_bf16.h>
#include <cstdint>

#define NT 365
#define NB 2048
#define NXD 32
#define HID 256
#define NG 1024
#define TSPLIT 184
#define STAGES 4
#define SA_BYTES 10240                 // A stage: 128 rows * 80B
#define STG_GX (SA_BYTES + 10240)      // + B 128 rows (gemm_gx only)
#define SMEM_GX (STAGES * STG_GX)      // 81920
// persistent step kernel smem: 4 A-stages + resident Whi/Wlo (64 x 528B each)
#define WROW 528
#define WSLAB (64 * WROW)              // 33792
#define SMEM_PS (STAGES * SA_BYTES + 2 * WSLAB)   // 40960 + 67584 = 108544

// ---- device-global scratch (no cudaMalloc allowed) ----
__device__ __nv_bfloat16 g_x0hi[(size_t)NT * NB * HID];
__device__ __nv_bfloat16 g_x0lo[(size_t)NT * NB * HID];
__device__ float g_gx0[(size_t)TSPLIT * NB * NG];
__device__ float g_gx1[(size_t)(NT - TSPLIT) * NB * NG];
__device__ __nv_bfloat16 g_hhi[2 * NB * HID];
__device__ __nv_bfloat16 g_hlo[2 * NB * HID];
__device__ __nv_bfloat16 g_wihHi[NG * HID], g_wihLo[NG * HID];  // permuted [C][k]
__device__ __nv_bfloat16 g_whhHi[NG * HID], g_whhLo[NG * HID];
__device__ float g_biasQ[NG];   // layout 4j+g
__device__ unsigned g_barG[16];    // per-batch-group monotonic arrival counters
__device__ volatile unsigned g_epochG[16];  // per-group released step count

// =====================================================================
// baseline-PTX helpers (sm_80-era: ldmatrix / mma.sync / cp.async)
// =====================================================================
__device__ __forceinline__ void ldsm4(uint32_t (&r)[4], uint32_t addr) {
    asm volatile("ldmatrix.sync.aligned.m8n8.x4.shared.b16 {%0,%1,%2,%3}, [%4];"
                 : "=r"(r[0]), "=r"(r[1]), "=r"(r[2]), "=r"(r[3]) : "r"(addr));
}
__device__ __forceinline__ void mma16816(float (&d)[4], const uint32_t (&a)[4],
                                         uint32_t b0, uint32_t b1) {
    asm volatile("mma.sync.aligned.m16n8k16.row.col.f32.bf16.bf16.f32 "
                 "{%0,%1,%2,%3}, {%4,%5,%6,%7}, {%8,%9}, {%0,%1,%2,%3};"
                 : "+f"(d[0]), "+f"(d[1]), "+f"(d[2]), "+f"(d[3])
                 : "r"(a[0]), "r"(a[1]), "r"(a[2]), "r"(a[3]), "r"(b0), "r"(b1));
}
__device__ __forceinline__ uint32_t smem_u32(const void* p) {
    return (uint32_t)__cvta_generic_to_shared(p);
}
__device__ __forceinline__ void cp16(uint32_t dst, const void* src) {
    asm volatile("cp.async.cg.shared.global [%0], [%1], 16;" :: "r"(dst), "l"(src));
}
__device__ __forceinline__ void prefetchL2(const void* p) {
    asm volatile("prefetch.global.L2 [%0];" :: "l"(p));
}
#define CPCOMMIT() asm volatile("cp.async.commit_group;" ::: "memory")
#define CPWAIT2()  asm volatile("cp.async.wait_group 2;" ::: "memory")

// =====================================================================
// gemm_gx core: 128x128 GEMM over virtual K=768 (3-phase hi/lo bf16),
// cp.async 4-stage pipeline, ONE sync per chunk (trailing sync removed:
// the leading sync already orders reads-of-stage-(kt-1) before its refill).
// =====================================================================
__device__ __forceinline__ void gemm_core_gx(
    float (*acc)[4][4],
    const __nv_bfloat16* __restrict__ Ahi, const __nv_bfloat16* __restrict__ Alo,
    size_t arow0,
    const __nv_bfloat16* __restrict__ Bhi, const __nv_bfloat16* __restrict__ Blo,
    size_t brow0,
    char* sm, int tid)
{
    const int lane = tid & 31, wid = tid >> 5;
    const int wm = wid >> 2, wn = wid & 3;
    const uint32_t sbase = smem_u32(sm);

#pragma unroll
    for (int a = 0; a < 4; ++a)
#pragma unroll
        for (int b = 0; b < 4; ++b)
#pragma unroll
            for (int r = 0; r < 4; ++r) acc[a][b][r] = 0.f;

    auto issue = [&](int stage, int nk) {
        int ph = nk >> 3;
        int k0 = (nk & 7) * 32;
        const __nv_bfloat16* As = (ph == 1) ? Alo : Ahi;
        const __nv_bfloat16* Bs = (ph == 2) ? Blo : Bhi;
        uint32_t dst = sbase + stage * STG_GX;
#pragma unroll
        for (int i = 0; i < 2; ++i) {
            int id = tid + i * 256;
            int row = id >> 2, seg = id & 3;
            cp16(dst + row * 80 + seg * 16,
                 As + arow0 + (size_t)row * HID + k0 + seg * 8);
        }
#pragma unroll
        for (int i = 0; i < 2; ++i) {
            int id = tid + i * 256;
            int row = id >> 2, seg = id & 3;
            cp16(dst + SA_BYTES + row * 80 + seg * 16,
                 Bs + brow0 + (size_t)row * HID + k0 + seg * 8);
        }
    };

#pragma unroll
    for (int s = 0; s < STAGES - 1; ++s) { issue(s, s); CPCOMMIT(); }

#pragma unroll 1
    for (int kt = 0; kt < 24; ++kt) {
        CPWAIT2();
        __syncthreads();
        if (kt + STAGES - 1 < 24) issue((kt + STAGES - 1) & (STAGES - 1), kt + STAGES - 1);
        CPCOMMIT();

        uint32_t abase = sbase + (kt & (STAGES - 1)) * STG_GX;
        uint32_t bbase = abase + SA_BYTES;
#pragma unroll
        for (int kk = 0; kk < 2; ++kk) {
            uint32_t af[4][4], bf[2][4];
#pragma unroll
            for (int mi = 0; mi < 4; ++mi)
                ldsm4(af[mi], abase + (wm * 64 + mi * 16 + (lane & 15)) * 80
                                    + kk * 32 + (lane >> 4) * 16);
#pragma unroll
            for (int np = 0; np < 2; ++np)
                ldsm4(bf[np], bbase + (wn * 32 + np * 16 + (lane & 15)) * 80
                                    + kk * 32 + (lane >> 4) * 16);
#pragma unroll
            for (int mi = 0; mi < 4; ++mi)
#pragma unroll
                for (int np = 0; np < 2; ++np) {
                    mma16816(acc[mi][2 * np],     af[mi], bf[np][0], bf[np][2]);
                    mma16816(acc[mi][2 * np + 1], af[mi], bf[np][1], bf[np][3]);
                }
        }
    }
}

// =====================================================================
// init: zero h buffers, reset group barriers, preset out = b_out
// =====================================================================
__global__ void init_kernel(const float* __restrict__ b_out, float* __restrict__ out) {
    int i = blockIdx.x * blockDim.x + threadIdx.x;
    int stride = gridDim.x * blockDim.x;
    __nv_bfloat16 z = __float2bfloat16(0.f);
    for (int k = i; k < 2 * NB * HID; k += stride) { g_hhi[k] = z; g_hlo[k] = z; }
    float b0 = b_out[0];
    for (int k = i; k < NT * NB; k += stride) out[k] = b0;
    if (i < 16) { g_barG[i] = 0; g_epochG[i] = 0; }
}

// =====================================================================
// weight prep (unchanged): C>>5-based gate permutation + hi/lo split
// =====================================================================
__global__ void prep_w(const float* __restrict__ w_ih, const float* __restrict__ w_hh,
                       const float* __restrict__ b_ih, const float* __restrict__ b_hh) {
    int C = blockIdx.x, k = threadIdx.x;
    int blk32 = C >> 5, r2 = C & 31, ni = r2 >> 3, p = r2 & 7;
    int j = blk32 * 8 + (ni >> 1) * 4 + (p >> 1);
    int g = ((ni & 1) << 1) | (p & 1);
    int src = g * HID + j;
    float vih = w_ih[(size_t)src * HID + k];
    float vhh = w_hh[(size_t)src * HID + k];
    __nv_bfloat16 h1 = __float2bfloat16_rn(vih);
    g_wihHi[(size_t)C * HID + k] = h1;
    g_wihLo[(size_t)C * HID + k] = __float2bfloat16_rn(vih - __bfloat162float(h1));
    __nv_bfloat16 h2 = __float2bfloat16_rn(vhh);
    g_whhHi[(size_t)C * HID + k] = h2;
    g_whhLo[(size_t)C * HID + k] = __float2bfloat16_rn(vhh - __bfloat162float(h2));
    if (k == 0) g_biasQ[4 * j + g] = b_ih[src] + b_hh[src];
}

// =====================================================================
// input projection (unchanged)
// =====================================================================
__global__ void __launch_bounds__(256) input_proj(const float* __restrict__ x,
                                                  const float* __restrict__ w_in,
                                                  const float* __restrict__ b_in) {
    __shared__ float xs[32][NXD];
    int tid = threadIdx.x;
    size_t row0 = (size_t)blockIdx.x * 32;
    const float* xsrc = x + row0 * NXD;
#pragma unroll
    for (int r = 0; r < 4; ++r) {
        int lin = tid + r * 256;
        xs[lin >> 5][lin & 31] = xsrc[lin];
    }
    float w[NXD];
#pragma unroll
    for (int n = 0; n < NXD; ++n) w[n] = w_in[tid * NXD + n];
    float b = b_in[tid];
    __syncthreads();
    __nv_bfloat16* dh = g_x0hi + row0 * HID + tid;
    __nv_bfloat16* dl = g_x0lo + row0 * HID + tid;
#pragma unroll 4
    for (int m = 0; m < 32; ++m) {
        float acc = b;
#pragma unroll
        for (int n = 0; n < NXD; ++n) acc = fmaf(xs[m][n], w[n], acc);
        float v = fmaxf(acc, 0.f);
        __nv_bfloat16 hi = __float2bfloat16_rn(v);
        dh[(size_t)m * HID] = hi;
        dl[(size_t)m * HID] = __float2bfloat16_rn(v - __bfloat162float(hi));
    }
}

// =====================================================================
// pre-GEMM: gx[R][4j+g] = x0[R] . w_ihP + biasQ ; tiles 128x128
// =====================================================================
__global__ void __launch_bounds__(256, 2) gemm_gx() {
    extern __shared__ __align__(16) char sm[];
    int tid = threadIdx.x, lane = tid & 31, wid = tid >> 5;
    int wm = wid >> 2, wn = wid & 3;
    int bx = blockIdx.x;
    size_t row0 = (size_t)blockIdx.y * 128;

    float acc[4][4][4];
    gemm_core_gx(acc, g_x0hi, g_x0lo, row0 * HID,
                 g_wihHi, g_wihLo, (size_t)bx * 128 * HID, sm, tid);

    float* gx; size_t R0;
    if (row0 < (size_t)TSPLIT * NB) { gx = g_gx0; R0 = row0; }
    else { gx = g_gx1; R0 = row0 - (size_t)TSPLIT * NB; }

    int q = lane >> 2;
#pragma unroll
    for (int np = 0; np < 2; ++np) {
        int jl = wn * 8 + np * 4 + (lane & 3);
        float4 bv = *(const float4*)(g_biasQ + bx * 128 + jl * 4);
#pragma unroll
        for (int mi = 0; mi < 4; ++mi) {
            size_t R = R0 + wm * 64 + mi * 16 + q;
#pragma unroll
            for (int hf = 0; hf < 2; ++hf) {
                float4 v;
                v.x = acc[mi][2 * np][2 * hf + 0] + bv.x;
                v.y = acc[mi][2 * np][2 * hf + 1] + bv.y;
                v.z = acc[mi][2 * np + 1][2 * hf + 0] + bv.z;
                v.w = acc[mi][2 * np + 1][2 * hf + 1] + bv.w;
                *(float4*)(gx + (R + hf * 8) * NG + bx * 128 + jl * 4) = v;
            }
        }
    }
}

// =====================================================================
// PERSISTENT recurrent kernel: all 365 steps in one launch.
// 256 CTAs: bx = cta>>4 (16 col-tiles of 64 gate-cols), by = cta&15
// (16 batch-tiles of 128 rows). Only the 16 CTAs sharing `by` exchange
// h -> per-group 16-CTA barrier (monotonic counters). gx tile prefetched
// to L2 at step start. One __syncthreads per K-chunk.
// =====================================================================
__global__ void __launch_bounds__(256, 2) lstm_persist(const float* __restrict__ w_out,
                                                       float* __restrict__ out) {
    extern __shared__ __align__(16) char sm[];
    char* wsm = sm + STAGES * SA_BYTES;
    const uint32_t sbase = smem_u32(sm);
    const uint32_t wbase = sbase + STAGES * SA_BYTES;

    int tid = threadIdx.x, lane = tid & 31, wid = tid >> 5;
    int wm = wid >> 1, wn = wid & 1;
    int cta = blockIdx.x;
    int bx = cta >> 4, by = cta & 15;
    int b0 = by * 128;
    int q = lane >> 2, l2 = lane & 3;

    // ---- load resident weight slabs (64 cols x 256 k, hi & lo) ----
    {
        const __nv_bfloat16* WH = g_whhHi + (size_t)bx * 64 * HID;
        const __nv_bfloat16* WL = g_whhLo + (size_t)bx * 64 * HID;
#pragma unroll
        for (int i = 0; i < 8; ++i) {
            int id = tid + i * 256;
            int row = id >> 5, seg = id & 31;
            *(float4*)(wsm + row * WROW + seg * 16) =
                *(const float4*)(WH + (size_t)row * HID + seg * 8);
            *(float4*)(wsm + WSLAB + row * WROW + seg * 16) =
                *(const float4*)(WL + (size_t)row * HID + seg * 8);
        }
    }
    __syncthreads();

    // ---- persistent per-thread state ----
    float creg[8];
#pragma unroll
    for (int i = 0; i < 8; ++i) creg[i] = 0.f;
    float wo[2];
#pragma unroll
    for (int np = 0; np < 2; ++np) wo[np] = w_out[bx * 16 + wn * 8 + np * 4 + l2];

#pragma unroll 1
    for (int t = 0; t < NT; ++t) {
        const __nv_bfloat16* hhi = g_hhi + (size_t)(t & 1) * NB * HID;
        const __nv_bfloat16* hlo = g_hlo + (size_t)(t & 1) * NB * HID;
        __nv_bfloat16* hhiO = g_hhi + (size_t)((t + 1) & 1) * NB * HID;
        __nv_bfloat16* hloO = g_hlo + (size_t)((t + 1) & 1) * NB * HID;
        const float* gx = (t < TSPLIT) ? (g_gx0 + (size_t)t * NB * NG)
                                       : (g_gx1 + (size_t)(t - TSPLIT) * NB * NG);

        // prefetch this step's gx tile (independent of h): 256 x 128B lines
        {
            int row = tid >> 1, half = tid & 1;
            prefetchL2((const char*)(gx + (size_t)(b0 + row) * NG + bx * 64) + half * 128);
        }

        float acc[2][4][4];
#pragma unroll
        for (int a = 0; a < 2; ++a)
#pragma unroll
            for (int b = 0; b < 4; ++b)
#pragma unroll
                for (int r = 0; r < 4; ++r) acc[a][b][r] = 0.f;

        auto issueA = [&](int stage, int nk) {
            int ph = nk >> 3;
            int k0 = (nk & 7) * 32;
            const __nv_bfloat16* As = (ph == 1) ? hlo : hhi;
            uint32_t dst = sbase + stage * SA_BYTES;
#pragma unroll
            for (int i = 0; i < 2; ++i) {
                int id = tid + i * 256;
                int row = id >> 2, seg = id & 3;
                cp16(dst + row * 80 + seg * 16,
                     As + (size_t)(b0 + row) * HID + k0 + seg * 8);
            }
        };

#pragma unroll
        for (int s = 0; s < STAGES - 1; ++s) { issueA(s, s); CPCOMMIT(); }

#pragma unroll 1
        for (int kt = 0; kt < 24; ++kt) {
            CPWAIT2();
            __syncthreads();
            if (kt + STAGES - 1 < 24) issueA((kt + STAGES - 1) & (STAGES - 1), kt + STAGES - 1);
            CPCOMMIT();

            uint32_t abase = sbase + (kt & (STAGES - 1)) * SA_BYTES;
            int ph = kt >> 3;
            uint32_t bb = wbase + (ph == 2 ? WSLAB : 0);
            int k0b = (kt & 7) * 64;
#pragma unroll
            for (int kk = 0; kk < 2; ++kk) {
                uint32_t af[2][4], bf[2][4];
#pragma unroll
                for (int mi = 0; mi < 2; ++mi)
                    ldsm4(af[mi], abase + (wm * 32 + mi * 16 + (lane & 15)) * 80
                                        + kk * 32 + (lane >> 4) * 16);
#pragma unroll
                for (int np = 0; np < 2; ++np)
                    ldsm4(bf[np], bb + (wn * 32 + np * 16 + (lane & 15)) * WROW
                                     + k0b + kk * 32 + (lane >> 4) * 16);
#pragma unroll
                for (int mi = 0; mi < 2; ++mi)
#pragma unroll
                    for (int np = 0; np < 2; ++np) {
                        mma16816(acc[mi][2 * np],     af[mi], bf[np][0], bf[np][2]);
                        mma16816(acc[mi][2 * np + 1], af[mi], bf[np][1], bf[np][3]);
                    }
            }
        }

        // ---- fused epilogue: gates -> cell update (c in regs) ----
        float osum[2][2];
        osum[0][0] = osum[0][1] = osum[1][0] = osum[1][1] = 0.f;
#pragma unroll
        for (int np = 0; np < 2; ++np) {
            int j = bx * 16 + wn * 8 + np * 4 + l2;
#pragma unroll
            for (int mi = 0; mi < 2; ++mi) {
#pragma unroll
                for (int hf = 0; hf < 2; ++hf) {
                    int b = b0 + wm * 32 + mi * 16 + q + hf * 8;
                    float4 gv = *(const float4*)(gx + (size_t)b * NG + j * 4);
                    float gi = acc[mi][2 * np][2 * hf + 0] + gv.x;
                    float gf = acc[mi][2 * np][2 * hf + 1] + gv.y;
                    float gg = acc[mi][2 * np + 1][2 * hf + 0] + gv.z;
                    float go = acc[mi][2 * np + 1][2 * hf + 1] + gv.w;
                    float ii = 1.f / (1.f + __expf(-gi));
                    float ff = 1.f / (1.f + __expf(-gf));
                    float tg = tanhf(gg);
                    float oo = 1.f / (1.f + __expf(-go));
                    int ci = np * 4 + mi * 2 + hf;
                    float cn = ff * creg[ci] + ii * tg;
                    float hn = oo * tanhf(cn);
                    creg[ci] = cn;
                    size_t idx = (size_t)b * HID + j;
                    __nv_bfloat16 hh = __float2bfloat16_rn(hn);
                    hhiO[idx] = hh;
                    hloO[idx] = __float2bfloat16_rn(hn - __bfloat162float(hh));
                    osum[mi][hf] = fmaf(hn, wo[np], osum[mi][hf]);
                }
            }
        }
#pragma unroll
        for (int mi = 0; mi < 2; ++mi)
#pragma unroll
            for (int hf = 0; hf < 2; ++hf) {
                float v = osum[mi][hf];
                v += __shfl_xor_sync(0xffffffffu, v, 1);
                v += __shfl_xor_sync(0xffffffffu, v, 2);
                if (l2 == 0) {
                    int b = b0 + wm * 32 + mi * 16 + q + hf * 8;
                    atomicAdd(out + (size_t)t * NB + b, v);
                }
            }

        // ---- per-group (16 CTA) barrier: h of this batch-tile visible ----
        if (t < NT - 1) {
            __syncthreads();
            if (tid == 0) {
                __threadfence();
                unsigned arr = atomicAdd(&g_barG[by], 1u) + 1u;
                if (arr == 16u * (unsigned)(t + 1)) {
                    __threadfence();
                    g_epochG[by] = (unsigned)(t + 1);
                } else {
                    unsigned e;
                    do {
                        __nanosleep(32);
                        asm volatile("ld.acquire.gpu.u32 %0, [%1];"
                                     : "=r"(e) : "l"((const unsigned*)&g_epochG[by]) : "memory");
                    } while (e < (unsigned)(t + 1));
                }
            }
            __syncthreads();
        }
    }
}

// =====================================================================
extern "C" void kernel_launch(void* const* d_in, const int* in_sizes, int n_in,
                              void* d_out, int out_size) {
    const float* x     = (const float*)d_in[0];
    const float* w_in  = (const float*)d_in[1];
    const float* b_in  = (const float*)d_in[2];
    const float* w_ih  = (const float*)d_in[3];
    const float* w_hh  = (const float*)d_in[4];
    const float* b_ih  = (const float*)d_in[5];
    const float* b_hh  = (const float*)d_in[6];
    const float* w_out = (const float*)d_in[7];
    const float* b_out = (const float*)d_in[8];
    float* out = (float*)d_out;

    static bool attr_done = false;
    if (!attr_done) {
        cudaFuncSetAttribute(gemm_gx, cudaFuncAttributeMaxDynamicSharedMemorySize, SMEM_GX);
        cudaFuncSetAttribute(lstm_persist, cudaFuncAttributeMaxDynamicSharedMemorySize, SMEM_PS);
        attr_done = true;
    }

    init_kernel<<<1024, 256>>>(b_out, out);
    prep_w<<<NG, HID>>>(w_ih, w_hh, b_ih, b_hh);
    input_proj<<<(NT * NB) / 32, 256>>>(x, w_in, b_in);
    gemm_gx<<<dim3(8, (NT * NB) / 128), 256, SMEM_GX>>>();
    lstm_persist<<<256, 256, SMEM_PS>>>(w_out, out);
}

// round 13
// speedup vs baseline: 3.8113x; 1.8405x over previous
#include <cuda_runtime.h>
#include <cuda_fp16.h>
#include <cstdint>

#define NT 365
#define NB 2048
#define NXD 32
#define HID 256
#define NG 1024
#define TSPLIT 184
#define STAGES 4
#define SA_BYTES 10240                 // A stage: 128 rows * 80B
#define STG_GX (SA_BYTES + 10240)      // + B 128 rows (gemm_gx only)
#define SMEM_GX (STAGES * STG_GX)      // 81920
// persistent step kernel smem: 4 A-stages + resident W (64 x 528B)
#define WROW 528
#define WSLAB (64 * WROW)              // 33792
#define SMEM_PS (STAGES * SA_BYTES + WSLAB)   // 40960 + 33792 = 74752

// ---- device-global scratch (no cudaMalloc allowed) ----
__device__ __half g_x0[(size_t)NT * NB * HID];            // 383 MB
__device__ float g_gx0[(size_t)TSPLIT * NB * NG];         // 1.54 GB
__device__ float g_gx1[(size_t)(NT - TSPLIT) * NB * NG];  // 1.52 GB
__device__ __half g_h[2 * NB * HID];
__device__ __half g_wih[NG * HID];     // permuted [C][k]
__device__ __half g_whh[NG * HID];
__device__ float g_biasQ[NG];          // layout 4j+g
__device__ unsigned g_barG[16];        // per-batch-group monotonic arrival counters
__device__ volatile unsigned g_epochG[16];

// =====================================================================
// baseline-PTX helpers (sm_80-era: ldmatrix / mma.sync / cp.async)
// =====================================================================
__device__ __forceinline__ void ldsm4(uint32_t (&r)[4], uint32_t addr) {
    asm volatile("ldmatrix.sync.aligned.m8n8.x4.shared.b16 {%0,%1,%2,%3}, [%4];"
                 : "=r"(r[0]), "=r"(r[1]), "=r"(r[2]), "=r"(r[3]) : "r"(addr));
}
__device__ __forceinline__ void mma16816(float (&d)[4], const uint32_t (&a)[4],
                                         uint32_t b0, uint32_t b1) {
    asm volatile("mma.sync.aligned.m16n8k16.row.col.f32.f16.f16.f32 "
                 "{%0,%1,%2,%3}, {%4,%5,%6,%7}, {%8,%9}, {%0,%1,%2,%3};"
                 : "+f"(d[0]), "+f"(d[1]), "+f"(d[2]), "+f"(d[3])
                 : "r"(a[0]), "r"(a[1]), "r"(a[2]), "r"(a[3]), "r"(b0), "r"(b1));
}
__device__ __forceinline__ uint32_t smem_u32(const void* p) {
    return (uint32_t)__cvta_generic_to_shared(p);
}
__device__ __forceinline__ void cp16(uint32_t dst, const void* src) {
    asm volatile("cp.async.cg.shared.global [%0], [%1], 16;" :: "r"(dst), "l"(src));
}
__device__ __forceinline__ void prefetchL2(const void* p) {
    asm volatile("prefetch.global.L2 [%0];" :: "l"(p));
}
#define CPCOMMIT() asm volatile("cp.async.commit_group;" ::: "memory")
#define CPWAIT2()  asm volatile("cp.async.wait_group 2;" ::: "memory")

// =====================================================================
// gemm_gx core: 128x128 GEMM, K=256 fp16 single-product,
// cp.async 4-stage pipeline, one sync per chunk.
// =====================================================================
__device__ __forceinline__ void gemm_core_gx(
    float (*acc)[4][4],
    const __half* __restrict__ A, size_t arow0,
    const __half* __restrict__ B, size_t brow0,
    char* sm, int tid)
{
    const int lane = tid & 31, wid = tid >> 5;
    const int wm = wid >> 2, wn = wid & 3;
    const uint32_t sbase = smem_u32(sm);

#pragma unroll
    for (int a = 0; a < 4; ++a)
#pragma unroll
        for (int b = 0; b < 4; ++b)
#pragma unroll
            for (int r = 0; r < 4; ++r) acc[a][b][r] = 0.f;

    auto issue = [&](int stage, int nk) {
        int k0 = nk * 32;
        uint32_t dst = sbase + stage * STG_GX;
#pragma unroll
        for (int i = 0; i < 2; ++i) {
            int id = tid + i * 256;
            int row = id >> 2, seg = id & 3;
            cp16(dst + row * 80 + seg * 16,
                 A + arow0 + (size_t)row * HID + k0 + seg * 8);
        }
#pragma unroll
        for (int i = 0; i < 2; ++i) {
            int id = tid + i * 256;
            int row = id >> 2, seg = id & 3;
            cp16(dst + SA_BYTES + row * 80 + seg * 16,
                 B + brow0 + (size_t)row * HID + k0 + seg * 8);
        }
    };

#pragma unroll
    for (int s = 0; s < STAGES - 1; ++s) { issue(s, s); CPCOMMIT(); }

#pragma unroll 1
    for (int kt = 0; kt < 8; ++kt) {
        CPWAIT2();
        __syncthreads();
        if (kt + STAGES - 1 < 8) issue((kt + STAGES - 1) & (STAGES - 1), kt + STAGES - 1);
        CPCOMMIT();

        uint32_t abase = sbase + (kt & (STAGES - 1)) * STG_GX;
        uint32_t bbase = abase + SA_BYTES;
#pragma unroll
        for (int kk = 0; kk < 2; ++kk) {
            uint32_t af[4][4], bf[2][4];
#pragma unroll
            for (int mi = 0; mi < 4; ++mi)
                ldsm4(af[mi], abase + (wm * 64 + mi * 16 + (lane & 15)) * 80
                                    + kk * 32 + (lane >> 4) * 16);
#pragma unroll
            for (int np = 0; np < 2; ++np)
                ldsm4(bf[np], bbase + (wn * 32 + np * 16 + (lane & 15)) * 80
                                    + kk * 32 + (lane >> 4) * 16);
#pragma unroll
            for (int mi = 0; mi < 4; ++mi)
#pragma unroll
                for (int np = 0; np < 2; ++np) {
                    mma16816(acc[mi][2 * np],     af[mi], bf[np][0], bf[np][2]);
                    mma16816(acc[mi][2 * np + 1], af[mi], bf[np][1], bf[np][3]);
                }
        }
    }
}

// =====================================================================
// init: zero h buffers, reset group barriers, preset out = b_out
// =====================================================================
__global__ void init_kernel(const float* __restrict__ b_out, float* __restrict__ out) {
    int i = blockIdx.x * blockDim.x + threadIdx.x;
    int stride = gridDim.x * blockDim.x;
    __half z = __float2half(0.f);
    for (int k = i; k < 2 * NB * HID; k += stride) g_h[k] = z;
    float b0 = b_out[0];
    for (int k = i; k < NT * NB; k += stride) out[k] = b0;
    if (i < 16) { g_barG[i] = 0; g_epochG[i] = 0; }
}

// =====================================================================
// weight prep: C>>5-based gate permutation, fp16
// =====================================================================
__global__ void prep_w(const float* __restrict__ w_ih, const float* __restrict__ w_hh,
                       const float* __restrict__ b_ih, const float* __restrict__ b_hh) {
    int C = blockIdx.x, k = threadIdx.x;
    int blk32 = C >> 5, r2 = C & 31, ni = r2 >> 3, p = r2 & 7;
    int j = blk32 * 8 + (ni >> 1) * 4 + (p >> 1);
    int g = ((ni & 1) << 1) | (p & 1);
    int src = g * HID + j;
    g_wih[(size_t)C * HID + k] = __float2half_rn(w_ih[(size_t)src * HID + k]);
    g_whh[(size_t)C * HID + k] = __float2half_rn(w_hh[(size_t)src * HID + k]);
    if (k == 0) g_biasQ[4 * j + g] = b_ih[src] + b_hh[src];
}

// =====================================================================
// input projection: x0 = relu(x @ w_in^T + b_in), fp16
// =====================================================================
__global__ void __launch_bounds__(256) input_proj(const float* __restrict__ x,
                                                  const float* __restrict__ w_in,
                                                  const float* __restrict__ b_in) {
    __shared__ float xs[32][NXD];
    int tid = threadIdx.x;
    size_t row0 = (size_t)blockIdx.x * 32;
    const float* xsrc = x + row0 * NXD;
#pragma unroll
    for (int r = 0; r < 4; ++r) {
        int lin = tid + r * 256;
        xs[lin >> 5][lin & 31] = xsrc[lin];
    }
    float w[NXD];
#pragma unroll
    for (int n = 0; n < NXD; ++n) w[n] = w_in[tid * NXD + n];
    float b = b_in[tid];
    __syncthreads();
    __half* dh = g_x0 + row0 * HID + tid;
#pragma unroll 4
    for (int m = 0; m < 32; ++m) {
        float acc = b;
#pragma unroll
        for (int n = 0; n < NXD; ++n) acc = fmaf(xs[m][n], w[n], acc);
        dh[(size_t)m * HID] = __float2half_rn(fmaxf(acc, 0.f));
    }
}

// =====================================================================
// pre-GEMM: gx[R][4j+g] = x0[R] . w_ihP + biasQ ; tiles 128x128
// =====================================================================
__global__ void __launch_bounds__(256, 2) gemm_gx() {
    extern __shared__ __align__(16) char sm[];
    int tid = threadIdx.x, lane = tid & 31, wid = tid >> 5;
    int wm = wid >> 2, wn = wid & 3;
    int bx = blockIdx.x;
    size_t row0 = (size_t)blockIdx.y * 128;

    float acc[4][4][4];
    gemm_core_gx(acc, g_x0, row0 * HID, g_wih, (size_t)bx * 128 * HID, sm, tid);

    float* gx; size_t R0;
    if (row0 < (size_t)TSPLIT * NB) { gx = g_gx0; R0 = row0; }
    else { gx = g_gx1; R0 = row0 - (size_t)TSPLIT * NB; }

    int q = lane >> 2;
#pragma unroll
    for (int np = 0; np < 2; ++np) {
        int jl = wn * 8 + np * 4 + (lane & 3);
        float4 bv = *(const float4*)(g_biasQ + bx * 128 + jl * 4);
#pragma unroll
        for (int mi = 0; mi < 4; ++mi) {
            size_t R = R0 + wm * 64 + mi * 16 + q;
#pragma unroll
            for (int hf = 0; hf < 2; ++hf) {
                float4 v;
                v.x = acc[mi][2 * np][2 * hf + 0] + bv.x;
                v.y = acc[mi][2 * np][2 * hf + 1] + bv.y;
                v.z = acc[mi][2 * np + 1][2 * hf + 0] + bv.z;
                v.w = acc[mi][2 * np + 1][2 * hf + 1] + bv.w;
                *(float4*)(gx + (R + hf * 8) * NG + bx * 128 + jl * 4) = v;
            }
        }
    }
}

// =====================================================================
// PERSISTENT recurrent kernel: all 365 steps in one launch.
// 256 CTAs: bx = cta>>4 (16 col-tiles of 64 gate-cols), by = cta&15
// (16 batch-tiles of 128 rows). K=256 fp16 single product, 8 chunks.
// =====================================================================
__global__ void __launch_bounds__(256, 2) lstm_persist(const float* __restrict__ w_out,
                                                       float* __restrict__ out) {
    extern __shared__ __align__(16) char sm[];
    char* wsm = sm + STAGES * SA_BYTES;
    const uint32_t sbase = smem_u32(sm);
    const uint32_t wbase = sbase + STAGES * SA_BYTES;

    int tid = threadIdx.x, lane = tid & 31, wid = tid >> 5;
    int wm = wid >> 1, wn = wid & 1;
    int cta = blockIdx.x;
    int bx = cta >> 4, by = cta & 15;
    int b0 = by * 128;
    int q = lane >> 2, l2 = lane & 3;

    // ---- load resident weight slab (64 cols x 256 k, fp16) ----
    {
        const __half* WH = g_whh + (size_t)bx * 64 * HID;
#pragma unroll
        for (int i = 0; i < 8; ++i) {
            int id = tid + i * 256;
            int row = id >> 5, seg = id & 31;
            *(float4*)(wsm + row * WROW + seg * 16) =
                *(const float4*)(WH + (size_t)row * HID + seg * 8);
        }
    }
    __syncthreads();

    // ---- persistent per-thread state ----
    float creg[8];
#pragma unroll
    for (int i = 0; i < 8; ++i) creg[i] = 0.f;
    float wo[2];
#pragma unroll
    for (int np = 0; np < 2; ++np) wo[np] = w_out[bx * 16 + wn * 8 + np * 4 + l2];

#pragma unroll 1
    for (int t = 0; t < NT; ++t) {
        const __half* hin = g_h + (size_t)(t & 1) * NB * HID;
        __half* hout = g_h + (size_t)((t + 1) & 1) * NB * HID;
        const float* gx = (t < TSPLIT) ? (g_gx0 + (size_t)t * NB * NG)
                                       : (g_gx1 + (size_t)(t - TSPLIT) * NB * NG);

        // prefetch this step's gx tile (independent of h)
        {
            int row = tid >> 1, half = tid & 1;
            prefetchL2((const char*)(gx + (size_t)(b0 + row) * NG + bx * 64) + half * 128);
        }

        float acc[2][4][4];
#pragma unroll
        for (int a = 0; a < 2; ++a)
#pragma unroll
            for (int b = 0; b < 4; ++b)
#pragma unroll
                for (int r = 0; r < 4; ++r) acc[a][b][r] = 0.f;

        auto issueA = [&](int stage, int nk) {
            int k0 = nk * 32;
            uint32_t dst = sbase + stage * SA_BYTES;
#pragma unroll
            for (int i = 0; i < 2; ++i) {
                int id = tid + i * 256;
                int row = id >> 2, seg = id & 3;
                cp16(dst + row * 80 + seg * 16,
                     hin + (size_t)(b0 + row) * HID + k0 + seg * 8);
            }
        };

#pragma unroll
        for (int s = 0; s < STAGES - 1; ++s) { issueA(s, s); CPCOMMIT(); }

#pragma unroll 1
        for (int kt = 0; kt < 8; ++kt) {
            CPWAIT2();
            __syncthreads();
            if (kt + STAGES - 1 < 8) issueA((kt + STAGES - 1) & (STAGES - 1), kt + STAGES - 1);
            CPCOMMIT();

            uint32_t abase = sbase + (kt & (STAGES - 1)) * SA_BYTES;
            int k0b = kt * 64;
#pragma unroll
            for (int kk = 0; kk < 2; ++kk) {
                uint32_t af[2][4], bf[2][4];
#pragma unroll
                for (int mi = 0; mi < 2; ++mi)
                    ldsm4(af[mi], abase + (wm * 32 + mi * 16 + (lane & 15)) * 80
                                        + kk * 32 + (lane >> 4) * 16);
#pragma unroll
                for (int np = 0; np < 2; ++np)
                    ldsm4(bf[np], wbase + (wn * 32 + np * 16 + (lane & 15)) * WROW
                                     + k0b + kk * 32 + (lane >> 4) * 16);
#pragma unroll
                for (int mi = 0; mi < 2; ++mi)
#pragma unroll
                    for (int np = 0; np < 2; ++np) {
                        mma16816(acc[mi][2 * np],     af[mi], bf[np][0], bf[np][2]);
                        mma16816(acc[mi][2 * np + 1], af[mi], bf[np][1], bf[np][3]);
                    }
            }
        }

        // ---- fused epilogue: gates -> cell update (c in regs) ----
        float osum[2][2];
        osum[0][0] = osum[0][1] = osum[1][0] = osum[1][1] = 0.f;
#pragma unroll
        for (int np = 0; np < 2; ++np) {
            int j = bx * 16 + wn * 8 + np * 4 + l2;
#pragma unroll
            for (int mi = 0; mi < 2; ++mi) {
#pragma unroll
                for (int hf = 0; hf < 2; ++hf) {
                    int b = b0 + wm * 32 + mi * 16 + q + hf * 8;
                    float4 gv = *(const float4*)(gx + (size_t)b * NG + j * 4);
                    float gi = acc[mi][2 * np][2 * hf + 0] + gv.x;
                    float gf = acc[mi][2 * np][2 * hf + 1] + gv.y;
                    float gg = acc[mi][2 * np + 1][2 * hf + 0] + gv.z;
                    float go = acc[mi][2 * np + 1][2 * hf + 1] + gv.w;
                    float ii = 1.f / (1.f + __expf(-gi));
                    float ff = 1.f / (1.f + __expf(-gf));
                    float tg = tanhf(gg);
                    float oo = 1.f / (1.f + __expf(-go));
                    int ci = np * 4 + mi * 2 + hf;
                    float cn = ff * creg[ci] + ii * tg;
                    float hn = oo * tanhf(cn);
                    creg[ci] = cn;
                    hout[(size_t)b * HID + j] = __float2half_rn(hn);
                    osum[mi][hf] = fmaf(hn, wo[np], osum[mi][hf]);
                }
            }
        }
#pragma unroll
        for (int mi = 0; mi < 2; ++mi)
#pragma unroll
            for (int hf = 0; hf < 2; ++hf) {
                float v = osum[mi][hf];
                v += __shfl_xor_sync(0xffffffffu, v, 1);
                v += __shfl_xor_sync(0xffffffffu, v, 2);
                if (l2 == 0) {
                    int b = b0 + wm * 32 + mi * 16 + q + hf * 8;
                    atomicAdd(out + (size_t)t * NB + b, v);
                }
            }

        // ---- per-group (16 CTA) barrier ----
        if (t < NT - 1) {
            __syncthreads();
            if (tid == 0) {
                __threadfence();
                unsigned arr = atomicAdd(&g_barG[by], 1u) + 1u;
                if (arr == 16u * (unsigned)(t + 1)) {
                    __threadfence();
                    g_epochG[by] = (unsigned)(t + 1);
                } else {
                    unsigned e;
                    do {
                        __nanosleep(32);
                        asm volatile("ld.acquire.gpu.u32 %0, [%1];"
                                     : "=r"(e) : "l"((const unsigned*)&g_epochG[by]) : "memory");
                    } while (e < (unsigned)(t + 1));
                }
            }
            __syncthreads();
        }
    }
}

// =====================================================================
extern "C" void kernel_launch(void* const* d_in, const int* in_sizes, int n_in,
                              void* d_out, int out_size) {
    const float* x     = (const float*)d_in[0];
    const float* w_in  = (const float*)d_in[1];
    const float* b_in  = (const float*)d_in[2];
    const float* w_ih  = (const float*)d_in[3];
    const float* w_hh  = (const float*)d_in[4];
    const float* b_ih  = (const float*)d_in[5];
    const float* b_hh  = (const float*)d_in[6];
    const float* w_out = (const float*)d_in[7];
    const float* b_out = (const float*)d_in[8];
    float* out = (float*)d_out;

    static bool attr_done = false;
    if (!attr_done) {
        cudaFuncSetAttribute(gemm_gx, cudaFuncAttributeMaxDynamicSharedMemorySize, SMEM_GX);
        cudaFuncSetAttribute(lstm_persist, cudaFuncAttributeMaxDynamicSharedMemorySize, SMEM_PS);
        attr_done = true;
    }

    init_kernel<<<1024, 256>>>(b_out, out);
    prep_w<<<NG, HID>>>(w_ih, w_hh, b_ih, b_hh);
    input_proj<<<(NT * NB) / 32, 256>>>(x, w_in, b_in);
    gemm_gx<<<dim3(8, (NT * NB) / 128), 256, SMEM_GX>>>();
    lstm_persist<<<256, 256, SMEM_PS>>>(w_out, out);
}